// round 11
// baseline (speedup 1.0000x reference)
#include <cuda_runtime.h>
#include <cuda_bf16.h>
#include <cstdint>

#define BB     128
#define NNODE  512
#define FIN_   2
#define COUT_  64
#define CIN_   66
#define BF     8448     // BB * CIN_
#define KPAD   512      // padded concat-K (462 -> 512, zeros)

// ---------------- scratch (static device globals) ---------------------------
static __device__ float g_ADP[2][NNODE * NNODE];
static __device__ float g_V  [NNODE * BB * 128];
static __device__ __align__(16) float g_ATf[4][NNODE * NNODE];      // AT float (k_sq B-op)
static __device__ __align__(16) float g_A2P[2][4][NNODE * NNODE];   // A^2 K-half partials
// split operands: 0=A0T,1=A1T,2=adp1T,3=adp2T,4=A0^2T,5=A1^2T,6=adp1^2T,7=adp2^2T
static __device__ __align__(16) __nv_bfloat16 g_ATh[8][NNODE * NNODE];
static __device__ __align__(16) __nv_bfloat16 g_ATl[8][NNODE * NNODE];
static __device__ __align__(16) __nv_bfloat16 g_XTh[BF * NNODE];
static __device__ __align__(16) __nv_bfloat16 g_XTl[BF * NNODE];
// pre-split concatenated H for the output GEMM: row = n*128+b, k = chunk*66+f
static __device__ __align__(16) __nv_bfloat16 g_Hh[(size_t)NNODE * BB * KPAD];
static __device__ __align__(16) __nv_bfloat16 g_Hl[(size_t)NNODE * BB * KPAD];
// transposed, padded, split weights: [n][KPAD]
static __device__ __align__(16) __nv_bfloat16 g_W1h[128 * KPAD];
static __device__ __align__(16) __nv_bfloat16 g_W1l[128 * KPAD];
static __device__ __align__(16) __nv_bfloat16 g_W2h[64 * KPAD];
static __device__ __align__(16) __nv_bfloat16 g_W2l[64 * KPAD];

// ---------------- PTX helpers -----------------------------------------------
__device__ __forceinline__ uint32_t smem_u32(const void* p) {
    uint32_t a;
    asm("{ .reg .u64 t; cvta.to.shared.u64 t, %1; cvt.u32.u64 %0, t; }" : "=r"(a) : "l"(p));
    return a;
}
#define SWZ128(off) ((off) ^ (((off) >> 3) & 0x70))

#define CP_ASYNC16(sm, gp) \
    asm volatile("cp.async.cg.shared.global [%0], [%1], 16;" :: "r"(sm), "l"(gp))
#define CP_COMMIT() asm volatile("cp.async.commit_group;" ::: "memory")
#define CP_WAIT(n)  asm volatile("cp.async.wait_group %0;" :: "n"(n) : "memory")

__device__ __forceinline__ void ldsm_x4(uint32_t* r, uint32_t addr) {
    asm volatile("ldmatrix.sync.aligned.m8n8.x4.shared.b16 {%0,%1,%2,%3}, [%4];"
                 : "=r"(r[0]), "=r"(r[1]), "=r"(r[2]), "=r"(r[3]) : "r"(addr));
}
__device__ __forceinline__ void ldsm_x2(uint32_t* r, uint32_t addr) {
    asm volatile("ldmatrix.sync.aligned.m8n8.x2.shared.b16 {%0,%1}, [%2];"
                 : "=r"(r[0]), "=r"(r[1]) : "r"(addr));
}
__device__ __forceinline__ void mma16816(float* c, const uint32_t* a, const uint32_t* b) {
    asm volatile("mma.sync.aligned.m16n8k16.row.col.f32.bf16.bf16.f32 "
                 "{%0,%1,%2,%3}, {%4,%5,%6,%7}, {%8,%9}, {%0,%1,%2,%3};"
                 : "+f"(c[0]), "+f"(c[1]), "+f"(c[2]), "+f"(c[3])
                 : "r"(a[0]), "r"(a[1]), "r"(a[2]), "r"(a[3]), "r"(b[0]), "r"(b[1]));
}

// ---------------- FFMA2 helpers (k_sq) --------------------------------------
__device__ __forceinline__ void ffma2(unsigned long long &d, unsigned long long a,
                                      unsigned long long b) {
    asm("fma.rn.f32x2 %0, %1, %2, %0;" : "+l"(d) : "l"(a), "l"(b));
}
__device__ __forceinline__ unsigned long long bcast2(float x) {
    unsigned long long r;
    asm("mov.b64 %0, {%1, %1};" : "=l"(r) : "f"(x));
    return r;
}
__device__ __forceinline__ float2 unpk2(unsigned long long v) {
    float lo, hi;
    asm("mov.b64 {%0, %1}, %2;" : "=f"(lo), "=f"(hi) : "l"(v));
    return make_float2(lo, hi);
}

// ---------------- adaptive adjacency ----------------------------------------
__global__ void k_adp(const float* __restrict__ nv1a, const float* __restrict__ nv2a,
                      const float* __restrict__ nv1b, const float* __restrict__ nv2b) {
    const int which = blockIdx.y;
    const float* nv1 = which ? nv1b : nv1a;
    const float* nv2 = which ? nv2b : nv2a;
    const int n = blockIdx.x, m = threadIdx.x;
    float w[10];
#pragma unroll
    for (int t = 0; t < 10; t++) w[t] = nv1[n * 10 + t];
    float v = 0.f;
#pragma unroll
    for (int t = 0; t < 10; t++) v += w[t] * nv2[t * NNODE + m];
    v = fmaxf(v, 0.f);
    __shared__ float red[512];
    red[m] = v; __syncthreads();
    for (int s = 256; s > 0; s >>= 1) { if (m < s) red[m] = fmaxf(red[m], red[m + s]); __syncthreads(); }
    float mx = red[0]; __syncthreads();
    float e = __expf(v - mx);
    red[m] = e; __syncthreads();
    for (int s = 256; s > 0; s >>= 1) { if (m < s) red[m] += red[m + s]; __syncthreads(); }
    g_ADP[which][n * NNODE + m] = e / red[0];
}

// ---------------- A transpose + float AT + bf16 split -----------------------
__global__ void k_prepA(const float* __restrict__ A0, const float* __restrict__ A1) {
    const int a = blockIdx.z;
    const float* __restrict__ src = (a == 0) ? A0 : (a == 1) ? A1 : g_ADP[a - 2];
    __shared__ float t[32][33];
    const int mb = blockIdx.x * 32, nb = blockIdx.y * 32;
    const int tx = threadIdx.x & 31, ty = threadIdx.x >> 5;
#pragma unroll
    for (int r = 0; r < 32; r += 8)
        t[ty + r][tx] = src[(nb + ty + r) * NNODE + mb + tx];
    __syncthreads();
#pragma unroll
    for (int r = 0; r < 32; r += 8) {
        float v = t[tx][ty + r];                       // A[nb+tx][mb+ty+r]
        __nv_bfloat16 h = __float2bfloat16(v);
        float rem = v - __bfloat162float(h);
        int o = (mb + ty + r) * NNODE + nb + tx;       // AT[m][n]
        g_ATf[a][o] = v;
        g_ATh[a][o] = h;
        g_ATl[a][o] = __float2bfloat16(rem);
    }
}

// ---------------- A^2 partials (fp32 FFMA2, split-K=2) ----------------------
// A2T[m][n] = sum_p A[p][m] * ATf[p][n]; this kernel does one K-half (256).
// grid (4, 4, 8): z = q*2 + khalf
__global__ void __launch_bounds__(256, 2)
k_sq(const float* __restrict__ A0, const float* __restrict__ A1) {
    const int q = blockIdx.z >> 1;
    const int kh = blockIdx.z & 1;
    const float* __restrict__ A = (q == 0) ? A0 : (q == 1) ? A1 : g_ADP[q - 2];
    const float* __restrict__ B = g_ATf[q];
    float* __restrict__ C = g_A2P[kh][q];
    const int kbase = kh * 256;

    __shared__ __align__(16) float As[2][16][128];
    __shared__ __align__(16) float Bs[2][16][128];

    const int tid = threadIdx.x;
    const int m0 = blockIdx.y * 128;
    const int j0 = blockIdx.x * 128;
    const int tx = tid & 15, ty = tid >> 4;
    const int mm = ty * 8, jj = tx * 8;
    const int lr = tid >> 5;
    const int lc = (tid & 31) * 4;

    unsigned long long acc[8][4];
#pragma unroll
    for (int i = 0; i < 8; i++)
#pragma unroll
        for (int j = 0; j < 4; j++) acc[i][j] = 0ULL;

    float4 ra0, ra1, rb0, rb1;
    ra0 = *(const float4*)(A + (kbase + lr) * 512 + m0 + lc);
    ra1 = *(const float4*)(A + (kbase + 8 + lr) * 512 + m0 + lc);
    rb0 = *(const float4*)(B + (kbase + lr) * 512 + j0 + lc);
    rb1 = *(const float4*)(B + (kbase + 8 + lr) * 512 + j0 + lc);
    *(float4*)&As[0][lr][lc] = ra0;
    *(float4*)&As[0][8 + lr][lc] = ra1;
    *(float4*)&Bs[0][lr][lc] = rb0;
    *(float4*)&Bs[0][8 + lr][lc] = rb1;
    __syncthreads();

    int buf = 0;
    for (int t = 0; t < 16; t++) {
        if (t < 15) {
            const int k0 = kbase + (t + 1) * 16;
            ra0 = *(const float4*)(A + (k0 + lr) * 512 + m0 + lc);
            ra1 = *(const float4*)(A + (k0 + 8 + lr) * 512 + m0 + lc);
            rb0 = *(const float4*)(B + (k0 + lr) * 512 + j0 + lc);
            rb1 = *(const float4*)(B + (k0 + 8 + lr) * 512 + j0 + lc);
        }
#pragma unroll
        for (int kk = 0; kk < 16; kk++) {
            const unsigned long long* bp = (const unsigned long long*)&Bs[buf][kk][jj];
            unsigned long long bv0 = bp[0], bv1 = bp[1], bv2 = bp[2], bv3 = bp[3];
#pragma unroll
            for (int i = 0; i < 8; i++) {
                unsigned long long av = bcast2(As[buf][kk][mm + i]);
                ffma2(acc[i][0], av, bv0);
                ffma2(acc[i][1], av, bv1);
                ffma2(acc[i][2], av, bv2);
                ffma2(acc[i][3], av, bv3);
            }
        }
        if (t < 15) {
            const int nb = buf ^ 1;
            *(float4*)&As[nb][lr][lc] = ra0;
            *(float4*)&As[nb][8 + lr][lc] = ra1;
            *(float4*)&Bs[nb][lr][lc] = rb0;
            *(float4*)&Bs[nb][8 + lr][lc] = rb1;
            __syncthreads();
            buf = nb;
        }
    }

#pragma unroll
    for (int i = 0; i < 8; i++) {
        float2* cp = (float2*)(C + (m0 + mm + i) * 512 + j0 + jj);
#pragma unroll
        for (int j = 0; j < 4; j++) cp[j] = unpk2(acc[i][j]);
    }
}

// ---------------- sum A^2 partials + bf16 split ------------------------------
__global__ void k_splitA2() {
    int idx = blockIdx.x * 256 + threadIdx.x;          // over 4 * 512 * 512
    if (idx >= 4 * NNODE * NNODE) return;
    int q = idx >> 18, o = idx & (NNODE * NNODE - 1);
    float v = g_A2P[0][q][o] + g_A2P[1][q][o];
    __nv_bfloat16 h = __float2bfloat16(v);
    g_ATh[4 + q][o] = h;
    g_ATl[4 + q][o] = __float2bfloat16(v - __bfloat162float(h));
}

// ---------------- W transpose + pad + bf16 split ----------------------------
__global__ void k_prepW(const float* __restrict__ W1, const float* __restrict__ W2) {
    const int z = blockIdx.y;
    const int BN = z ? 64 : 128;
    const float* __restrict__ W = z ? W2 : W1;
    __nv_bfloat16* __restrict__ dh = z ? g_W2h : g_W1h;
    __nv_bfloat16* __restrict__ dl = z ? g_W2l : g_W1l;
    int idx = blockIdx.x * 256 + threadIdx.x;
    if (idx >= KPAD * BN) return;
    int k = idx / BN, n = idx - k * BN;
    float v = (k < 462) ? W[k * BN + n] : 0.f;
    __nv_bfloat16 h = __float2bfloat16(v);
    dh[n * KPAD + k] = h;
    dl[n * KPAD + k] = __float2bfloat16(v - __bfloat162float(h));
}

// ---------------- fused source build: pack + transpose + split + H chunk 0 --
__global__ void k_src(int which, const float* __restrict__ inp,
                      const float* __restrict__ st) {
    __shared__ float t[32][33];
    const int jb = blockIdx.x * 32, nb = blockIdx.y * 32;
    const int tx = threadIdx.x & 31, ty = threadIdx.x >> 5;
#pragma unroll
    for (int r = 0; r < 32; r += 8) {
        const int n = nb + ty + r;
        const int j = jb + tx;
        const int b = j / CIN_, f = j - b * CIN_;
        float v;
        if (f < FIN_) {
            v = inp[(b * NNODE + n) * FIN_ + f];
        } else {
            const int c = f - FIN_;
            const float s = st[(b * NNODE + n) * COUT_ + c];
            v = which ? g_V[((size_t)n * BB + b) * 128 + c] * s : s;
        }
        t[ty + r][tx] = v;
        const size_t ho = ((size_t)n * BB + b) * KPAD + f;
        const __nv_bfloat16 h = __float2bfloat16(v);
        g_Hh[ho] = h;
        g_Hl[ho] = __float2bfloat16(v - __bfloat162float(h));
    }
    __syncthreads();
#pragma unroll
    for (int r = 0; r < 32; r += 8) {
        const float v = t[tx][ty + r];
        const __nv_bfloat16 h = __float2bfloat16(v);
        const size_t o = (size_t)(jb + ty + r) * NNODE + nb + tx;
        g_XTh[o] = h;
        g_XTl[o] = __float2bfloat16(v - __bfloat162float(h));
    }
}

// ---------------- diffusion GEMM on HMMA (6 supports, BM=128 BN=256) --------
#define OFF_AH 0
#define OFF_AL 16384
#define OFF_BH 32768
#define OFF_BL 65536
#define BUFSZ  98304
#define DIFF_SMEM (2 * BUFSZ)   // 196608

__device__ __forceinline__ void diff_load(uint32_t sb, int buf,
                                          const __nv_bfloat16* Ah, const __nv_bfloat16* Al,
                                          int m0, int j0, int n0, int tid) {
    uint32_t base = sb + buf * BUFSZ;
#pragma unroll
    for (int i = 0; i < 2; i++) {          // A: 1024 chunks each for h,l
        int v = tid + i * 512;
        int row = v >> 3, ks = v & 7;
        uint32_t sw = SWZ128((uint32_t)(row * 128 + ks * 16));
        size_t go = (size_t)(m0 + row) * NNODE + n0 + ks * 8;
        CP_ASYNC16(base + OFF_AH + sw, Ah + go);
        CP_ASYNC16(base + OFF_AL + sw, Al + go);
    }
#pragma unroll
    for (int i = 0; i < 4; i++) {          // B: 2048 chunks each for h,l
        int v = tid + i * 512;
        int row = v >> 3, ks = v & 7;
        uint32_t sw = SWZ128((uint32_t)(row * 128 + ks * 16));
        size_t go = (size_t)(j0 + row) * NNODE + n0 + ks * 8;
        CP_ASYNC16(base + OFF_BH + sw, g_XTh + go);
        CP_ASYNC16(base + OFF_BL + sw, g_XTl + go);
    }
}

// which: GCN index (0 -> adp1, 1 -> adp2). z: 0..5 = {A0,A1,adp,A0^2,A1^2,adp^2}
__global__ void __launch_bounds__(512, 1) k_diff_mma(int which) {
    extern __shared__ __align__(1024) char smem[];
    const uint32_t sb = smem_u32(smem);
    const int tid = threadIdx.x, wid = tid >> 5, lane = tid & 31;
    const int z = blockIdx.z;
    const int m0 = blockIdx.y * 128;
    const int j0 = blockIdx.x * 256;
    const int aIdx = (z == 0) ? 0 : (z == 1) ? 1 : (z == 2) ? (2 + which)
                   : (z == 3) ? 4 : (z == 4) ? 5 : (6 + which);
    const int ch = (z < 3) ? (1 + 2 * z) : (2 + 2 * (z - 3));

    const __nv_bfloat16* __restrict__ Ah = g_ATh[aIdx];
    const __nv_bfloat16* __restrict__ Al = g_ATl[aIdx];

    const int warp_m = wid & 3;            // 4 warps along M (32 rows each)
    const int warp_n = wid >> 2;           // 4 warps along N (64 cols each)

    float acc[2][8][4];
#pragma unroll
    for (int mi = 0; mi < 2; mi++)
#pragma unroll
        for (int ni = 0; ni < 8; ni++)
#pragma unroll
            for (int q = 0; q < 4; q++) acc[mi][ni][q] = 0.f;

    diff_load(sb, 0, Ah, Al, m0, j0, 0, tid);
    CP_COMMIT();

    for (int kt = 0; kt < 8; kt++) {
        if (kt < 7) {
            diff_load(sb, (kt + 1) & 1, Ah, Al, m0, j0, (kt + 1) * 64, tid);
            CP_COMMIT();
            CP_WAIT(1);
        } else {
            CP_WAIT(0);
        }
        __syncthreads();

        const uint32_t base = sb + (kt & 1) * BUFSZ;
#pragma unroll
        for (int kk = 0; kk < 4; kk++) {
            uint32_t ah[2][4], al[2][4];
#pragma unroll
            for (int mi = 0; mi < 2; mi++) {
                uint32_t off = (uint32_t)((warp_m * 32 + mi * 16 + (lane & 15)) * 128
                                          + kk * 32 + (lane >> 4) * 16);
                uint32_t sw = SWZ128(off);
                ldsm_x4(ah[mi], base + OFF_AH + sw);
                ldsm_x4(al[mi], base + OFF_AL + sw);
            }
#pragma unroll
            for (int ni = 0; ni < 8; ni++) {
                uint32_t bh[2], bl[2];
                uint32_t off = (uint32_t)((warp_n * 64 + ni * 8 + (lane & 7)) * 128
                                          + kk * 32 + ((lane >> 3) & 1) * 16);
                uint32_t sw = SWZ128(off);
                ldsm_x2(bh, base + OFF_BH + sw);
                ldsm_x2(bl, base + OFF_BL + sw);
#pragma unroll
                for (int mi = 0; mi < 2; mi++) {
                    mma16816(acc[mi][ni], ah[mi], bh);
                    mma16816(acc[mi][ni], ah[mi], bl);
                    mma16816(acc[mi][ni], al[mi], bh);
                }
            }
        }
        __syncthreads();
    }

    // epilogue: write split H chunk
    const int g = lane >> 2, t = lane & 3;
#pragma unroll
    for (int mi = 0; mi < 2; mi++) {
        const int row = m0 + warp_m * 32 + mi * 16 + g;
#pragma unroll
        for (int ni = 0; ni < 8; ni++) {
            const int col = j0 + warp_n * 64 + ni * 8 + t * 2;   // always even
            const int b = col / CIN_, f = col - b * CIN_;
#pragma unroll
            for (int h2 = 0; h2 < 2; h2++) {
                const int rr = row + h2 * 8;
                const float vx = acc[mi][ni][h2 * 2 + 0];
                const float vy = acc[mi][ni][h2 * 2 + 1];
                const size_t ho = ((size_t)rr * BB + b) * KPAD + ch * CIN_ + f;
                __nv_bfloat162 hh = __floats2bfloat162_rn(vx, vy);
                *(__nv_bfloat162*)(g_Hh + ho) = hh;
                float lx = vx - __bfloat162float(hh.x);
                float ly = vy - __bfloat162float(hh.y);
                *(__nv_bfloat162*)(g_Hl + ho) = __floats2bfloat162_rn(lx, ly);
            }
        }
    }
}

// ---------------- output GEMM on HMMA + fused epilogue ----------------------
template <int BN, int ACT>
__global__ void __launch_bounds__(256, 1)
k_out_mma(const float* __restrict__ bias, const float* __restrict__ state,
          float* __restrict__ outp) {
    constexpr int NI = BN / 16;
    constexpr int ASZ = 16384;
    constexpr int BSZ = BN * 64 * 2;
    constexpr int OAH = 0, OAL = ASZ, OBH = 2 * ASZ, OBL = 2 * ASZ + BSZ;
    constexpr int KBUF = 2 * ASZ + 2 * BSZ;

    extern __shared__ __align__(1024) char smem[];
    const uint32_t sb = smem_u32(smem);
    const int tid = threadIdx.x, wid = tid >> 5, lane = tid & 31;
    const int row0 = blockIdx.x * 128;

    const __nv_bfloat16* __restrict__ Wh = (BN == 128) ? g_W1h : g_W2h;
    const __nv_bfloat16* __restrict__ Wl = (BN == 128) ? g_W1l : g_W2l;

    const int warp_m = wid & 3;
    const int warp_n = wid >> 2;

    float acc[2][NI][4];
#pragma unroll
    for (int mi = 0; mi < 2; mi++)
#pragma unroll
        for (int ni = 0; ni < NI; ni++)
#pragma unroll
            for (int q = 0; q < 4; q++) acc[mi][ni][q] = 0.f;

    auto load_tile = [&](int buf, int k0) {
        uint32_t base = sb + buf * KBUF;
#pragma unroll
        for (int i = 0; i < 4; i++) {
            int v = tid + i * 256;
            int row = v >> 3, ks = v & 7;
            uint32_t sw = SWZ128((uint32_t)(row * 128 + ks * 16));
            size_t go = (size_t)(row0 + row) * KPAD + k0 + ks * 8;
            CP_ASYNC16(base + OAH + sw, g_Hh + go);
            CP_ASYNC16(base + OAL + sw, g_Hl + go);
        }
#pragma unroll
        for (int i = 0; i < BN * 8 / 256; i++) {
            int v = tid + i * 256;
            int row = v >> 3, ks = v & 7;
            uint32_t sw = SWZ128((uint32_t)(row * 128 + ks * 16));
            size_t go = (size_t)row * KPAD + k0 + ks * 8;
            CP_ASYNC16(base + OBH + sw, Wh + go);
            CP_ASYNC16(base + OBL + sw, Wl + go);
        }
    };

    load_tile(0, 0);
    CP_COMMIT();

    for (int kt = 0; kt < 8; kt++) {
        if (kt < 7) {
            load_tile((kt + 1) & 1, (kt + 1) * 64);
            CP_COMMIT();
            CP_WAIT(1);
        } else {
            CP_WAIT(0);
        }
        __syncthreads();

        const uint32_t base = sb + (kt & 1) * KBUF;
#pragma unroll
        for (int kk = 0; kk < 4; kk++) {
            uint32_t ah[2][4], al[2][4];
#pragma unroll
            for (int mi = 0; mi < 2; mi++) {
                uint32_t off = (uint32_t)((warp_m * 32 + mi * 16 + (lane & 15)) * 128
                                          + kk * 32 + (lane >> 4) * 16);
                uint32_t sw = SWZ128(off);
                ldsm_x4(ah[mi], base + OAH + sw);
                ldsm_x4(al[mi], base + OAL + sw);
            }
            uint32_t bh[NI][2], bl[NI][2];
#pragma unroll
            for (int ni = 0; ni < NI; ni++) {
                uint32_t off = (uint32_t)((warp_n * (BN / 2) + ni * 8 + (lane & 7)) * 128
                                          + kk * 32 + ((lane >> 3) & 1) * 16);
                uint32_t sw = SWZ128(off);
                ldsm_x2(bh[ni], base + OBH + sw);
                ldsm_x2(bl[ni], base + OBL + sw);
            }
#pragma unroll
            for (int mi = 0; mi < 2; mi++)
#pragma unroll
                for (int ni = 0; ni < NI; ni++) {
                    mma16816(acc[mi][ni], ah[mi], bh[ni]);
                    mma16816(acc[mi][ni], ah[mi], bl[ni]);
                    mma16816(acc[mi][ni], al[mi], bh[ni]);
                }
        }
        __syncthreads();
    }

    // fused epilogue
    const int g = lane >> 2, t = lane & 3;
#pragma unroll
    for (int mi = 0; mi < 2; mi++) {
        const int row = row0 + warp_m * 32 + mi * 16 + g;
#pragma unroll
        for (int ni = 0; ni < NI; ni++) {
            const int col = warp_n * (BN / 2) + ni * 8 + t * 2;
            const float b0 = bias[col], b1 = bias[col + 1];
#pragma unroll
            for (int h2 = 0; h2 < 2; h2++) {
                const int rr = row + h2 * 8;
                const float vx = acc[mi][ni][h2 * 2 + 0] + b0;
                const float vy = acc[mi][ni][h2 * 2 + 1] + b1;
                if (ACT == 0) {
                    *(float2*)(g_V + (size_t)rr * 128 + col) =
                        make_float2(1.f / (1.f + __expf(-vx)),
                                    1.f / (1.f + __expf(-vy)));
                } else {
                    const int n = rr >> 7, b = rr & 127;
                    const float c0 = tanhf(vx), c1 = tanhf(vy);
                    const float u0 = g_V[(size_t)rr * 128 + 64 + col];
                    const float u1 = g_V[(size_t)rr * 128 + 64 + col + 1];
                    const size_t si = ((size_t)b * NNODE + n) * COUT_ + col;
                    const float st0 = state[si], st1 = state[si + 1];
                    *(float2*)(outp + si) =
                        make_float2(u0 * st0 + (1.f - u0) * c0,
                                    u1 * st1 + (1.f - u1) * c1);
                }
            }
        }
    }
}

// ---------------- launch ----------------------------------------------------
extern "C" void kernel_launch(void* const* d_in, const int* in_sizes, int n_in,
                              void* d_out, int out_size) {
    const float* input = (const float*)d_in[0];
    const float* state = (const float*)d_in[1];
    const float* A0    = (const float*)d_in[2];
    const float* A1    = (const float*)d_in[3];
    const float* nv1_1 = (const float*)d_in[4];
    const float* nv2_1 = (const float*)d_in[5];
    const float* W1    = (const float*)d_in[6];
    const float* b1    = (const float*)d_in[7];
    const float* nv1_2 = (const float*)d_in[8];
    const float* nv2_2 = (const float*)d_in[9];
    const float* W2    = (const float*)d_in[10];
    const float* b2    = (const float*)d_in[11];
    float* outp = (float*)d_out;

    constexpr int KO128_SMEM = 2 * (2 * 16384 + 2 * 16384);   // 131072
    constexpr int KO64_SMEM  = 2 * (2 * 16384 + 2 * 8192);    //  98304
    cudaFuncSetAttribute(k_diff_mma, cudaFuncAttributeMaxDynamicSharedMemorySize, DIFF_SMEM);
    cudaFuncSetAttribute(k_out_mma<128, 0>, cudaFuncAttributeMaxDynamicSharedMemorySize, KO128_SMEM);
    cudaFuncSetAttribute(k_out_mma<64, 1>,  cudaFuncAttributeMaxDynamicSharedMemorySize, KO64_SMEM);

    const dim3 gDiff(BF / 256, NNODE / 128, 6);      // (33, 4, 6)
    const dim3 gSrc(BF / 32, NNODE / 32);

    k_adp<<<dim3(NNODE, 2), 512>>>(nv1_1, nv2_1, nv1_2, nv2_2);
    k_prepA<<<dim3(16, 16, 4), 256>>>(A0, A1);
    k_prepW<<<dim3((KPAD * 128 + 255) / 256, 2), 256>>>(W1, W2);
    k_sq<<<dim3(4, 4, 8), 256>>>(A0, A1);
    k_splitA2<<<(4 * NNODE * NNODE + 255) / 256, 256>>>();

    // GCN 1
    k_src<<<gSrc, 256>>>(0, input, state);
    k_diff_mma<<<gDiff, 512, DIFF_SMEM>>>(0);
    k_out_mma<128, 0><<<NNODE * BB / 128, 256, KO128_SMEM>>>(b1, state, nullptr);

    // GCN 2
    k_src<<<gSrc, 256>>>(1, input, state);
    k_diff_mma<<<gDiff, 512, DIFF_SMEM>>>(1);
    k_out_mma<64, 1><<<NNODE * BB / 128, 256, KO64_SMEM>>>(b2, state, outp);
}

// round 12
// speedup vs baseline: 1.1025x; 1.1025x over previous
#include <cuda_runtime.h>
#include <cuda_bf16.h>
#include <cstdint>

#define BB     128
#define NNODE  512
#define FIN_   2
#define COUT_  64
#define CIN_   66
#define BF     8448     // BB * CIN_
#define KPAD   512      // padded concat-K (462 -> 512, zeros)

// ---------------- scratch (static device globals) ---------------------------
static __device__ float g_ADP[2][NNODE * NNODE];
static __device__ float g_V  [NNODE * BB * 128];
static __device__ __align__(16) float g_ATf[4][NNODE * NNODE];      // AT float (k_sq B-op)
static __device__ __align__(16) float g_A2P[4][4][NNODE * NNODE];   // A^2 K-quarter partials
// split operands: 0=A0T,1=A1T,2=adp1T,3=adp2T,4=A0^2T,5=A1^2T,6=adp1^2T,7=adp2^2T
static __device__ __align__(16) __nv_bfloat16 g_ATh[8][NNODE * NNODE];
static __device__ __align__(16) __nv_bfloat16 g_ATl[8][NNODE * NNODE];
static __device__ __align__(16) __nv_bfloat16 g_XTh[BF * NNODE];
static __device__ __align__(16) __nv_bfloat16 g_XTl[BF * NNODE];
// pre-split concatenated H for the output GEMM: row = n*128+b, k = chunk*66+f
static __device__ __align__(16) __nv_bfloat16 g_Hh[(size_t)NNODE * BB * KPAD];
static __device__ __align__(16) __nv_bfloat16 g_Hl[(size_t)NNODE * BB * KPAD];
// transposed, padded, split weights: [n][KPAD]
static __device__ __align__(16) __nv_bfloat16 g_W1h[128 * KPAD];
static __device__ __align__(16) __nv_bfloat16 g_W1l[128 * KPAD];
static __device__ __align__(16) __nv_bfloat16 g_W2h[64 * KPAD];
static __device__ __align__(16) __nv_bfloat16 g_W2l[64 * KPAD];

// ---------------- PTX helpers -----------------------------------------------
__device__ __forceinline__ uint32_t smem_u32(const void* p) {
    uint32_t a;
    asm("{ .reg .u64 t; cvta.to.shared.u64 t, %1; cvt.u32.u64 %0, t; }" : "=r"(a) : "l"(p));
    return a;
}
#define SWZ128(off) ((off) ^ (((off) >> 3) & 0x70))

#define CP_ASYNC16(sm, gp) \
    asm volatile("cp.async.cg.shared.global [%0], [%1], 16;" :: "r"(sm), "l"(gp))
#define CP_COMMIT() asm volatile("cp.async.commit_group;" ::: "memory")
#define CP_WAIT(n)  asm volatile("cp.async.wait_group %0;" :: "n"(n) : "memory")

__device__ __forceinline__ void ldsm_x4(uint32_t* r, uint32_t addr) {
    asm volatile("ldmatrix.sync.aligned.m8n8.x4.shared.b16 {%0,%1,%2,%3}, [%4];"
                 : "=r"(r[0]), "=r"(r[1]), "=r"(r[2]), "=r"(r[3]) : "r"(addr));
}
__device__ __forceinline__ void ldsm_x2(uint32_t* r, uint32_t addr) {
    asm volatile("ldmatrix.sync.aligned.m8n8.x2.shared.b16 {%0,%1}, [%2];"
                 : "=r"(r[0]), "=r"(r[1]) : "r"(addr));
}
__device__ __forceinline__ void mma16816(float* c, const uint32_t* a, const uint32_t* b) {
    asm volatile("mma.sync.aligned.m16n8k16.row.col.f32.bf16.bf16.f32 "
                 "{%0,%1,%2,%3}, {%4,%5,%6,%7}, {%8,%9}, {%0,%1,%2,%3};"
                 : "+f"(c[0]), "+f"(c[1]), "+f"(c[2]), "+f"(c[3])
                 : "r"(a[0]), "r"(a[1]), "r"(a[2]), "r"(a[3]), "r"(b[0]), "r"(b[1]));
}

// ---------------- FFMA2 helpers (k_sq) --------------------------------------
__device__ __forceinline__ void ffma2(unsigned long long &d, unsigned long long a,
                                      unsigned long long b) {
    asm("fma.rn.f32x2 %0, %1, %2, %0;" : "+l"(d) : "l"(a), "l"(b));
}
__device__ __forceinline__ unsigned long long bcast2(float x) {
    unsigned long long r;
    asm("mov.b64 %0, {%1, %1};" : "=l"(r) : "f"(x));
    return r;
}
__device__ __forceinline__ float2 unpk2(unsigned long long v) {
    float lo, hi;
    asm("mov.b64 {%0, %1}, %2;" : "=f"(lo), "=f"(hi) : "l"(v));
    return make_float2(lo, hi);
}

// ---------------- adaptive adjacency ----------------------------------------
__global__ void k_adp(const float* __restrict__ nv1a, const float* __restrict__ nv2a,
                      const float* __restrict__ nv1b, const float* __restrict__ nv2b) {
    const int which = blockIdx.y;
    const float* nv1 = which ? nv1b : nv1a;
    const float* nv2 = which ? nv2b : nv2a;
    const int n = blockIdx.x, m = threadIdx.x;
    float w[10];
#pragma unroll
    for (int t = 0; t < 10; t++) w[t] = nv1[n * 10 + t];
    float v = 0.f;
#pragma unroll
    for (int t = 0; t < 10; t++) v += w[t] * nv2[t * NNODE + m];
    v = fmaxf(v, 0.f);
    __shared__ float red[512];
    red[m] = v; __syncthreads();
    for (int s = 256; s > 0; s >>= 1) { if (m < s) red[m] = fmaxf(red[m], red[m + s]); __syncthreads(); }
    float mx = red[0]; __syncthreads();
    float e = __expf(v - mx);
    red[m] = e; __syncthreads();
    for (int s = 256; s > 0; s >>= 1) { if (m < s) red[m] += red[m + s]; __syncthreads(); }
    g_ADP[which][n * NNODE + m] = e / red[0];
}

// ---------------- A transpose + float AT + bf16 split -----------------------
__global__ void k_prepA(const float* __restrict__ A0, const float* __restrict__ A1) {
    const int a = blockIdx.z;
    const float* __restrict__ src = (a == 0) ? A0 : (a == 1) ? A1 : g_ADP[a - 2];
    __shared__ float t[32][33];
    const int mb = blockIdx.x * 32, nb = blockIdx.y * 32;
    const int tx = threadIdx.x & 31, ty = threadIdx.x >> 5;
#pragma unroll
    for (int r = 0; r < 32; r += 8)
        t[ty + r][tx] = src[(nb + ty + r) * NNODE + mb + tx];
    __syncthreads();
#pragma unroll
    for (int r = 0; r < 32; r += 8) {
        float v = t[tx][ty + r];                       // A[nb+tx][mb+ty+r]
        __nv_bfloat16 h = __float2bfloat16(v);
        float rem = v - __bfloat162float(h);
        int o = (mb + ty + r) * NNODE + nb + tx;       // AT[m][n]
        g_ATf[a][o] = v;
        g_ATh[a][o] = h;
        g_ATl[a][o] = __float2bfloat16(rem);
    }
}

// ---------------- A^2 partials (fp32 FFMA2, split-K=4) ----------------------
// A2T[m][n] = sum_p A[p][m] * ATf[p][n]; this kernel does one K-quarter (128).
// grid (4, 4, 16): z = q*4 + kq
__global__ void __launch_bounds__(256, 2)
k_sq(const float* __restrict__ A0, const float* __restrict__ A1) {
    const int q = blockIdx.z >> 2;
    const int kq = blockIdx.z & 3;
    const float* __restrict__ A = (q == 0) ? A0 : (q == 1) ? A1 : g_ADP[q - 2];
    const float* __restrict__ B = g_ATf[q];
    float* __restrict__ C = g_A2P[kq][q];
    const int kbase = kq * 128;

    __shared__ __align__(16) float As[2][16][128];
    __shared__ __align__(16) float Bs[2][16][128];

    const int tid = threadIdx.x;
    const int m0 = blockIdx.y * 128;
    const int j0 = blockIdx.x * 128;
    const int tx = tid & 15, ty = tid >> 4;
    const int mm = ty * 8, jj = tx * 8;
    const int lr = tid >> 5;
    const int lc = (tid & 31) * 4;

    unsigned long long acc[8][4];
#pragma unroll
    for (int i = 0; i < 8; i++)
#pragma unroll
        for (int j = 0; j < 4; j++) acc[i][j] = 0ULL;

    float4 ra0, ra1, rb0, rb1;
    ra0 = *(const float4*)(A + (kbase + lr) * 512 + m0 + lc);
    ra1 = *(const float4*)(A + (kbase + 8 + lr) * 512 + m0 + lc);
    rb0 = *(const float4*)(B + (kbase + lr) * 512 + j0 + lc);
    rb1 = *(const float4*)(B + (kbase + 8 + lr) * 512 + j0 + lc);
    *(float4*)&As[0][lr][lc] = ra0;
    *(float4*)&As[0][8 + lr][lc] = ra1;
    *(float4*)&Bs[0][lr][lc] = rb0;
    *(float4*)&Bs[0][8 + lr][lc] = rb1;
    __syncthreads();

    int buf = 0;
    for (int t = 0; t < 8; t++) {
        if (t < 7) {
            const int k0 = kbase + (t + 1) * 16;
            ra0 = *(const float4*)(A + (k0 + lr) * 512 + m0 + lc);
            ra1 = *(const float4*)(A + (k0 + 8 + lr) * 512 + m0 + lc);
            rb0 = *(const float4*)(B + (k0 + lr) * 512 + j0 + lc);
            rb1 = *(const float4*)(B + (k0 + 8 + lr) * 512 + j0 + lc);
        }
#pragma unroll
        for (int kk = 0; kk < 16; kk++) {
            const unsigned long long* bp = (const unsigned long long*)&Bs[buf][kk][jj];
            unsigned long long bv0 = bp[0], bv1 = bp[1], bv2 = bp[2], bv3 = bp[3];
#pragma unroll
            for (int i = 0; i < 8; i++) {
                unsigned long long av = bcast2(As[buf][kk][mm + i]);
                ffma2(acc[i][0], av, bv0);
                ffma2(acc[i][1], av, bv1);
                ffma2(acc[i][2], av, bv2);
                ffma2(acc[i][3], av, bv3);
            }
        }
        if (t < 7) {
            const int nb = buf ^ 1;
            *(float4*)&As[nb][lr][lc] = ra0;
            *(float4*)&As[nb][8 + lr][lc] = ra1;
            *(float4*)&Bs[nb][lr][lc] = rb0;
            *(float4*)&Bs[nb][8 + lr][lc] = rb1;
            __syncthreads();
            buf = nb;
        }
    }

#pragma unroll
    for (int i = 0; i < 8; i++) {
        float2* cp = (float2*)(C + (m0 + mm + i) * 512 + j0 + jj);
#pragma unroll
        for (int j = 0; j < 4; j++) cp[j] = unpk2(acc[i][j]);
    }
}

// ---------------- sum A^2 partials + bf16 split ------------------------------
__global__ void k_splitA2() {
    int idx = blockIdx.x * 256 + threadIdx.x;          // over 4 * 512 * 512
    if (idx >= 4 * NNODE * NNODE) return;
    int q = idx >> 18, o = idx & (NNODE * NNODE - 1);
    float v = (g_A2P[0][q][o] + g_A2P[1][q][o]) + (g_A2P[2][q][o] + g_A2P[3][q][o]);
    __nv_bfloat16 h = __float2bfloat16(v);
    g_ATh[4 + q][o] = h;
    g_ATl[4 + q][o] = __float2bfloat16(v - __bfloat162float(h));
}

// ---------------- W transpose + pad + bf16 split ----------------------------
__global__ void k_prepW(const float* __restrict__ W1, const float* __restrict__ W2) {
    const int z = blockIdx.y;
    const int BN = z ? 64 : 128;
    const float* __restrict__ W = z ? W2 : W1;
    __nv_bfloat16* __restrict__ dh = z ? g_W2h : g_W1h;
    __nv_bfloat16* __restrict__ dl = z ? g_W2l : g_W1l;
    int idx = blockIdx.x * 256 + threadIdx.x;
    if (idx >= KPAD * BN) return;
    int k = idx / BN, n = idx - k * BN;
    float v = (k < 462) ? W[k * BN + n] : 0.f;
    __nv_bfloat16 h = __float2bfloat16(v);
    dh[n * KPAD + k] = h;
    dl[n * KPAD + k] = __float2bfloat16(v - __bfloat162float(h));
}

// ---------------- fused source build: pack + transpose + split + H chunk 0 --
__global__ void k_src(int which, const float* __restrict__ inp,
                      const float* __restrict__ st) {
    __shared__ float t[32][33];
    const int jb = blockIdx.x * 32, nb = blockIdx.y * 32;
    const int tx = threadIdx.x & 31, ty = threadIdx.x >> 5;
#pragma unroll
    for (int r = 0; r < 32; r += 8) {
        const int n = nb + ty + r;
        const int j = jb + tx;
        const int b = j / CIN_, f = j - b * CIN_;
        float v;
        if (f < FIN_) {
            v = inp[(b * NNODE + n) * FIN_ + f];
        } else {
            const int c = f - FIN_;
            const float s = st[(b * NNODE + n) * COUT_ + c];
            v = which ? g_V[((size_t)n * BB + b) * 128 + c] * s : s;
        }
        t[ty + r][tx] = v;
        const size_t ho = ((size_t)n * BB + b) * KPAD + f;
        const __nv_bfloat16 h = __float2bfloat16(v);
        g_Hh[ho] = h;
        g_Hl[ho] = __float2bfloat16(v - __bfloat162float(h));
    }
    __syncthreads();
#pragma unroll
    for (int r = 0; r < 32; r += 8) {
        const float v = t[tx][ty + r];
        const __nv_bfloat16 h = __float2bfloat16(v);
        const size_t o = (size_t)(jb + ty + r) * NNODE + nb + tx;
        g_XTh[o] = h;
        g_XTl[o] = __float2bfloat16(v - __bfloat162float(h));
    }
}

// ---------------- diffusion GEMM on HMMA (6 supports, BM=BN=128) ------------
#define OFF_AH 0
#define OFF_AL 16384
#define OFF_BH 32768
#define OFF_BL 49152
#define BUFSZ  65536
#define DIFF_SMEM (2 * BUFSZ)   // 131072

__device__ __forceinline__ void diff_load(uint32_t sb, int buf,
                                          const __nv_bfloat16* Ah, const __nv_bfloat16* Al,
                                          int m0, int j0, int n0, int tid) {
    uint32_t base = sb + buf * BUFSZ;
#pragma unroll
    for (int i = 0; i < 4; i++) {
        int v = tid + i * 256;
        int row = v >> 3, ks = v & 7;
        uint32_t sw = SWZ128((uint32_t)(row * 128 + ks * 16));
        size_t goA = (size_t)(m0 + row) * NNODE + n0 + ks * 8;
        size_t goB = (size_t)(j0 + row) * NNODE + n0 + ks * 8;
        CP_ASYNC16(base + OFF_AH + sw, Ah + goA);
        CP_ASYNC16(base + OFF_AL + sw, Al + goA);
        CP_ASYNC16(base + OFF_BH + sw, g_XTh + goB);
        CP_ASYNC16(base + OFF_BL + sw, g_XTl + goB);
    }
}

// which: GCN index (0 -> adp1, 1 -> adp2). z: 0..5 = {A0,A1,adp,A0^2,A1^2,adp^2}
__global__ void __launch_bounds__(256, 1) k_diff_mma(int which) {
    extern __shared__ __align__(1024) char smem[];
    const uint32_t sb = smem_u32(smem);
    const int tid = threadIdx.x, wid = tid >> 5, lane = tid & 31;
    const int z = blockIdx.z;
    const int m0 = blockIdx.y * 128;
    const int j0 = blockIdx.x * 128;
    const int aIdx = (z == 0) ? 0 : (z == 1) ? 1 : (z == 2) ? (2 + which)
                   : (z == 3) ? 4 : (z == 4) ? 5 : (6 + which);
    const int ch = (z < 3) ? (1 + 2 * z) : (2 + 2 * (z - 3));

    const __nv_bfloat16* __restrict__ Ah = g_ATh[aIdx];
    const __nv_bfloat16* __restrict__ Al = g_ATl[aIdx];

    const int warp_m = wid & 3;
    const int warp_n = wid >> 2;

    float acc[2][8][4];
#pragma unroll
    for (int mi = 0; mi < 2; mi++)
#pragma unroll
        for (int ni = 0; ni < 8; ni++)
#pragma unroll
            for (int q = 0; q < 4; q++) acc[mi][ni][q] = 0.f;

    diff_load(sb, 0, Ah, Al, m0, j0, 0, tid);
    CP_COMMIT();

    for (int kt = 0; kt < 8; kt++) {
        if (kt < 7) {
            diff_load(sb, (kt + 1) & 1, Ah, Al, m0, j0, (kt + 1) * 64, tid);
            CP_COMMIT();
            CP_WAIT(1);
        } else {
            CP_WAIT(0);
        }
        __syncthreads();

        const uint32_t base = sb + (kt & 1) * BUFSZ;
#pragma unroll
        for (int kk = 0; kk < 4; kk++) {
            uint32_t ah[2][4], al[2][4];
#pragma unroll
            for (int mi = 0; mi < 2; mi++) {
                uint32_t off = (uint32_t)((warp_m * 32 + mi * 16 + (lane & 15)) * 128
                                          + kk * 32 + (lane >> 4) * 16);
                uint32_t sw = SWZ128(off);
                ldsm_x4(ah[mi], base + OFF_AH + sw);
                ldsm_x4(al[mi], base + OFF_AL + sw);
            }
            uint32_t bh[8][2], bl[8][2];
#pragma unroll
            for (int ni = 0; ni < 8; ni++) {
                uint32_t off = (uint32_t)((warp_n * 64 + ni * 8 + (lane & 7)) * 128
                                          + kk * 32 + ((lane >> 3) & 1) * 16);
                uint32_t sw = SWZ128(off);
                ldsm_x2(bh[ni], base + OFF_BH + sw);
                ldsm_x2(bl[ni], base + OFF_BL + sw);
            }
#pragma unroll
            for (int mi = 0; mi < 2; mi++)
#pragma unroll
                for (int ni = 0; ni < 8; ni++) {
                    mma16816(acc[mi][ni], ah[mi], bh[ni]);
                    mma16816(acc[mi][ni], ah[mi], bl[ni]);
                    mma16816(acc[mi][ni], al[mi], bh[ni]);
                }
        }
        __syncthreads();
    }

    // epilogue: write split H chunk
    const int g = lane >> 2, t = lane & 3;
#pragma unroll
    for (int mi = 0; mi < 2; mi++) {
        const int row = m0 + warp_m * 32 + mi * 16 + g;
#pragma unroll
        for (int ni = 0; ni < 8; ni++) {
            const int col = j0 + warp_n * 64 + ni * 8 + t * 2;   // always even
            const int b = col / CIN_, f = col - b * CIN_;
#pragma unroll
            for (int h2 = 0; h2 < 2; h2++) {
                const int rr = row + h2 * 8;
                const float vx = acc[mi][ni][h2 * 2 + 0];
                const float vy = acc[mi][ni][h2 * 2 + 1];
                const size_t ho = ((size_t)rr * BB + b) * KPAD + ch * CIN_ + f;
                __nv_bfloat162 hh = __floats2bfloat162_rn(vx, vy);
                *(__nv_bfloat162*)(g_Hh + ho) = hh;
                float lx = vx - __bfloat162float(hh.x);
                float ly = vy - __bfloat162float(hh.y);
                *(__nv_bfloat162*)(g_Hl + ho) = __floats2bfloat162_rn(lx, ly);
            }
        }
    }
}

// ---------------- output GEMM on HMMA + fused epilogue ----------------------
template <int BN, int ACT>
__global__ void __launch_bounds__(256, 1)
k_out_mma(const float* __restrict__ bias, const float* __restrict__ state,
          float* __restrict__ outp) {
    constexpr int NI = BN / 16;
    constexpr int ASZ = 16384;
    constexpr int BSZ = BN * 64 * 2;
    constexpr int OAH = 0, OAL = ASZ, OBH = 2 * ASZ, OBL = 2 * ASZ + BSZ;
    constexpr int KBUF = 2 * ASZ + 2 * BSZ;

    extern __shared__ __align__(1024) char smem[];
    const uint32_t sb = smem_u32(smem);
    const int tid = threadIdx.x, wid = tid >> 5, lane = tid & 31;
    const int row0 = blockIdx.x * 128;

    const __nv_bfloat16* __restrict__ Wh = (BN == 128) ? g_W1h : g_W2h;
    const __nv_bfloat16* __restrict__ Wl = (BN == 128) ? g_W1l : g_W2l;

    const int warp_m = wid & 3;
    const int warp_n = wid >> 2;

    float acc[2][NI][4];
#pragma unroll
    for (int mi = 0; mi < 2; mi++)
#pragma unroll
        for (int ni = 0; ni < NI; ni++)
#pragma unroll
            for (int q = 0; q < 4; q++) acc[mi][ni][q] = 0.f;

    auto load_tile = [&](int buf, int k0) {
        uint32_t base = sb + buf * KBUF;
#pragma unroll
        for (int i = 0; i < 4; i++) {
            int v = tid + i * 256;
            int row = v >> 3, ks = v & 7;
            uint32_t sw = SWZ128((uint32_t)(row * 128 + ks * 16));
            size_t go = (size_t)(row0 + row) * KPAD + k0 + ks * 8;
            CP_ASYNC16(base + OAH + sw, g_Hh + go);
            CP_ASYNC16(base + OAL + sw, g_Hl + go);
        }
#pragma unroll
        for (int i = 0; i < BN * 8 / 256; i++) {
            int v = tid + i * 256;
            int row = v >> 3, ks = v & 7;
            uint32_t sw = SWZ128((uint32_t)(row * 128 + ks * 16));
            size_t go = (size_t)row * KPAD + k0 + ks * 8;
            CP_ASYNC16(base + OBH + sw, Wh + go);
            CP_ASYNC16(base + OBL + sw, Wl + go);
        }
    };

    load_tile(0, 0);
    CP_COMMIT();

    for (int kt = 0; kt < 8; kt++) {
        if (kt < 7) {
            load_tile((kt + 1) & 1, (kt + 1) * 64);
            CP_COMMIT();
            CP_WAIT(1);
        } else {
            CP_WAIT(0);
        }
        __syncthreads();

        const uint32_t base = sb + (kt & 1) * KBUF;
#pragma unroll
        for (int kk = 0; kk < 4; kk++) {
            uint32_t ah[2][4], al[2][4];
#pragma unroll
            for (int mi = 0; mi < 2; mi++) {
                uint32_t off = (uint32_t)((warp_m * 32 + mi * 16 + (lane & 15)) * 128
                                          + kk * 32 + (lane >> 4) * 16);
                uint32_t sw = SWZ128(off);
                ldsm_x4(ah[mi], base + OAH + sw);
                ldsm_x4(al[mi], base + OAL + sw);
            }
            uint32_t bh[NI][2], bl[NI][2];
#pragma unroll
            for (int ni = 0; ni < NI; ni++) {
                uint32_t off = (uint32_t)((warp_n * (BN / 2) + ni * 8 + (lane & 7)) * 128
                                          + kk * 32 + ((lane >> 3) & 1) * 16);
                uint32_t sw = SWZ128(off);
                ldsm_x2(bh[ni], base + OBH + sw);
                ldsm_x2(bl[ni], base + OBL + sw);
            }
#pragma unroll
            for (int mi = 0; mi < 2; mi++)
#pragma unroll
                for (int ni = 0; ni < NI; ni++) {
                    mma16816(acc[mi][ni], ah[mi], bh[ni]);
                    mma16816(acc[mi][ni], ah[mi], bl[ni]);
                    mma16816(acc[mi][ni], al[mi], bh[ni]);
                }
        }
        __syncthreads();
    }

    // fused epilogue
    const int g = lane >> 2, t = lane & 3;
#pragma unroll
    for (int mi = 0; mi < 2; mi++) {
        const int row = row0 + warp_m * 32 + mi * 16 + g;
#pragma unroll
        for (int ni = 0; ni < NI; ni++) {
            const int col = warp_n * (BN / 2) + ni * 8 + t * 2;
            const float b0 = bias[col], b1 = bias[col + 1];
#pragma unroll
            for (int h2 = 0; h2 < 2; h2++) {
                const int rr = row + h2 * 8;
                const float vx = acc[mi][ni][h2 * 2 + 0] + b0;
                const float vy = acc[mi][ni][h2 * 2 + 1] + b1;
                if (ACT == 0) {
                    *(float2*)(g_V + (size_t)rr * 128 + col) =
                        make_float2(1.f / (1.f + __expf(-vx)),
                                    1.f / (1.f + __expf(-vy)));
                } else {
                    const int n = rr >> 7, b = rr & 127;
                    const float c0 = tanhf(vx), c1 = tanhf(vy);
                    const float u0 = g_V[(size_t)rr * 128 + 64 + col];
                    const float u1 = g_V[(size_t)rr * 128 + 64 + col + 1];
                    const size_t si = ((size_t)b * NNODE + n) * COUT_ + col;
                    const float st0 = state[si], st1 = state[si + 1];
                    *(float2*)(outp + si) =
                        make_float2(u0 * st0 + (1.f - u0) * c0,
                                    u1 * st1 + (1.f - u1) * c1);
                }
            }
        }
    }
}

// ---------------- launch ----------------------------------------------------
extern "C" void kernel_launch(void* const* d_in, const int* in_sizes, int n_in,
                              void* d_out, int out_size) {
    const float* input = (const float*)d_in[0];
    const float* state = (const float*)d_in[1];
    const float* A0    = (const float*)d_in[2];
    const float* A1    = (const float*)d_in[3];
    const float* nv1_1 = (const float*)d_in[4];
    const float* nv2_1 = (const float*)d_in[5];
    const float* W1    = (const float*)d_in[6];
    const float* b1    = (const float*)d_in[7];
    const float* nv1_2 = (const float*)d_in[8];
    const float* nv2_2 = (const float*)d_in[9];
    const float* W2    = (const float*)d_in[10];
    const float* b2    = (const float*)d_in[11];
    float* outp = (float*)d_out;

    constexpr int KO128_SMEM = 2 * (2 * 16384 + 2 * 16384);   // 131072
    constexpr int KO64_SMEM  = 2 * (2 * 16384 + 2 * 8192);    //  98304
    cudaFuncSetAttribute(k_diff_mma, cudaFuncAttributeMaxDynamicSharedMemorySize, DIFF_SMEM);
    cudaFuncSetAttribute(k_out_mma<128, 0>, cudaFuncAttributeMaxDynamicSharedMemorySize, KO128_SMEM);
    cudaFuncSetAttribute(k_out_mma<64, 1>,  cudaFuncAttributeMaxDynamicSharedMemorySize, KO64_SMEM);

    const dim3 gDiff(BF / 128, NNODE / 128, 6);      // (66, 4, 6)
    const dim3 gSrc(BF / 32, NNODE / 32);

    k_adp<<<dim3(NNODE, 2), 512>>>(nv1_1, nv2_1, nv1_2, nv2_2);
    k_prepA<<<dim3(16, 16, 4), 256>>>(A0, A1);
    k_prepW<<<dim3((KPAD * 128 + 255) / 256, 2), 256>>>(W1, W2);
    k_sq<<<dim3(4, 4, 16), 256>>>(A0, A1);
    k_splitA2<<<(4 * NNODE * NNODE + 255) / 256, 256>>>();

    // GCN 1
    k_src<<<gSrc, 256>>>(0, input, state);
    k_diff_mma<<<gDiff, 256, DIFF_SMEM>>>(0);
    k_out_mma<128, 0><<<NNODE * BB / 128, 256, KO128_SMEM>>>(b1, state, nullptr);

    // GCN 2
    k_src<<<gSrc, 256>>>(1, input, state);
    k_diff_mma<<<gDiff, 256, DIFF_SMEM>>>(1);
    k_out_mma<64, 1><<<NNODE * BB / 128, 256, KO64_SMEM>>>(b2, state, outp);
}

// round 14
// speedup vs baseline: 1.1061x; 1.0032x over previous
#include <cuda_runtime.h>
#include <cuda_bf16.h>
#include <cstdint>

#define BB     128
#define NNODE  512
#define FIN_   2
#define COUT_  64
#define CIN_   66
#define BF     8448     // BB * CIN_
#define KPAD   512      // padded concat-K (462 -> 512, zeros)

// ---------------- scratch (static device globals) ---------------------------
static __device__ float g_ADP[2][NNODE * NNODE];
static __device__ float g_V  [NNODE * BB * 128];
static __device__ __align__(16) float g_ATf[4][NNODE * NNODE];      // AT float (k_sq B-op)
static __device__ __align__(16) float g_A2P[4][4][NNODE * NNODE];   // A^2 K-quarter partials
// split operands: 0=A0T,1=A1T,2=adp1T,3=adp2T,4=A0^2T,5=A1^2T,6=adp1^2T,7=adp2^2T
static __device__ __align__(16) __nv_bfloat16 g_ATh[8][NNODE * NNODE];
static __device__ __align__(16) __nv_bfloat16 g_ATl[8][NNODE * NNODE];
static __device__ __align__(16) __nv_bfloat16 g_XTh[BF * NNODE];
static __device__ __align__(16) __nv_bfloat16 g_XTl[BF * NNODE];
// pre-split concatenated H for the output GEMM: row = n*128+b, k = chunk*66+f
static __device__ __align__(16) __nv_bfloat16 g_Hh[(size_t)NNODE * BB * KPAD];
static __device__ __align__(16) __nv_bfloat16 g_Hl[(size_t)NNODE * BB * KPAD];
// transposed, padded, split weights: [n][KPAD]
static __device__ __align__(16) __nv_bfloat16 g_W1h[128 * KPAD];
static __device__ __align__(16) __nv_bfloat16 g_W1l[128 * KPAD];
static __device__ __align__(16) __nv_bfloat16 g_W2h[64 * KPAD];
static __device__ __align__(16) __nv_bfloat16 g_W2l[64 * KPAD];

// ---------------- PTX helpers -----------------------------------------------
__device__ __forceinline__ uint32_t smem_u32(const void* p) {
    uint32_t a;
    asm("{ .reg .u64 t; cvta.to.shared.u64 t, %1; cvt.u32.u64 %0, t; }" : "=r"(a) : "l"(p));
    return a;
}
#define SWZ128(off) ((off) ^ (((off) >> 3) & 0x70))
#define SWZ64(off)  ((off) ^ (((off) >> 3) & 0x30))

#define CP_ASYNC16(sm, gp) \
    asm volatile("cp.async.cg.shared.global [%0], [%1], 16;" :: "r"(sm), "l"(gp))
#define CP_COMMIT() asm volatile("cp.async.commit_group;" ::: "memory")
#define CP_WAIT(n)  asm volatile("cp.async.wait_group %0;" :: "n"(n) : "memory")

__device__ __forceinline__ void ldsm_x4(uint32_t* r, uint32_t addr) {
    asm volatile("ldmatrix.sync.aligned.m8n8.x4.shared.b16 {%0,%1,%2,%3}, [%4];"
                 : "=r"(r[0]), "=r"(r[1]), "=r"(r[2]), "=r"(r[3]) : "r"(addr));
}
__device__ __forceinline__ void ldsm_x2(uint32_t* r, uint32_t addr) {
    asm volatile("ldmatrix.sync.aligned.m8n8.x2.shared.b16 {%0,%1}, [%2];"
                 : "=r"(r[0]), "=r"(r[1]) : "r"(addr));
}
__device__ __forceinline__ void mma16816(float* c, const uint32_t* a, const uint32_t* b) {
    asm volatile("mma.sync.aligned.m16n8k16.row.col.f32.bf16.bf16.f32 "
                 "{%0,%1,%2,%3}, {%4,%5,%6,%7}, {%8,%9}, {%0,%1,%2,%3};"
                 : "+f"(c[0]), "+f"(c[1]), "+f"(c[2]), "+f"(c[3])
                 : "r"(a[0]), "r"(a[1]), "r"(a[2]), "r"(a[3]), "r"(b[0]), "r"(b[1]));
}

// ---------------- FFMA2 helpers (k_sq) --------------------------------------
__device__ __forceinline__ void ffma2(unsigned long long &d, unsigned long long a,
                                      unsigned long long b) {
    asm("fma.rn.f32x2 %0, %1, %2, %0;" : "+l"(d) : "l"(a), "l"(b));
}
__device__ __forceinline__ unsigned long long bcast2(float x) {
    unsigned long long r;
    asm("mov.b64 %0, {%1, %1};" : "=l"(r) : "f"(x));
    return r;
}
__device__ __forceinline__ float2 unpk2(unsigned long long v) {
    float lo, hi;
    asm("mov.b64 {%0, %1}, %2;" : "=f"(lo), "=f"(hi) : "l"(v));
    return make_float2(lo, hi);
}

// ---------------- adaptive adjacency ----------------------------------------
__global__ void k_adp(const float* __restrict__ nv1a, const float* __restrict__ nv2a,
                      const float* __restrict__ nv1b, const float* __restrict__ nv2b) {
    const int which = blockIdx.y;
    const float* nv1 = which ? nv1b : nv1a;
    const float* nv2 = which ? nv2b : nv2a;
    const int n = blockIdx.x, m = threadIdx.x;
    float w[10];
#pragma unroll
    for (int t = 0; t < 10; t++) w[t] = nv1[n * 10 + t];
    float v = 0.f;
#pragma unroll
    for (int t = 0; t < 10; t++) v += w[t] * nv2[t * NNODE + m];
    v = fmaxf(v, 0.f);
    __shared__ float red[512];
    red[m] = v; __syncthreads();
    for (int s = 256; s > 0; s >>= 1) { if (m < s) red[m] = fmaxf(red[m], red[m + s]); __syncthreads(); }
    float mx = red[0]; __syncthreads();
    float e = __expf(v - mx);
    red[m] = e; __syncthreads();
    for (int s = 256; s > 0; s >>= 1) { if (m < s) red[m] += red[m + s]; __syncthreads(); }
    g_ADP[which][n * NNODE + m] = e / red[0];
}

// ---------------- A transpose + float AT + bf16 split -----------------------
__global__ void k_prepA(const float* __restrict__ A0, const float* __restrict__ A1) {
    const int a = blockIdx.z;
    const float* __restrict__ src = (a == 0) ? A0 : (a == 1) ? A1 : g_ADP[a - 2];
    __shared__ float t[32][33];
    const int mb = blockIdx.x * 32, nb = blockIdx.y * 32;
    const int tx = threadIdx.x & 31, ty = threadIdx.x >> 5;
#pragma unroll
    for (int r = 0; r < 32; r += 8)
        t[ty + r][tx] = src[(nb + ty + r) * NNODE + mb + tx];
    __syncthreads();
#pragma unroll
    for (int r = 0; r < 32; r += 8) {
        float v = t[tx][ty + r];                       // A[nb+tx][mb+ty+r]
        __nv_bfloat16 h = __float2bfloat16(v);
        float rem = v - __bfloat162float(h);
        int o = (mb + ty + r) * NNODE + nb + tx;       // AT[m][n]
        g_ATf[a][o] = v;
        g_ATh[a][o] = h;
        g_ATl[a][o] = __float2bfloat16(rem);
    }
}

// ---------------- A^2 partials (fp32 FFMA2, split-K=4) ----------------------
__global__ void __launch_bounds__(256, 2)
k_sq(const float* __restrict__ A0, const float* __restrict__ A1) {
    const int q = blockIdx.z >> 2;
    const int kq = blockIdx.z & 3;
    const float* __restrict__ A = (q == 0) ? A0 : (q == 1) ? A1 : g_ADP[q - 2];
    const float* __restrict__ B = g_ATf[q];
    float* __restrict__ C = g_A2P[kq][q];
    const int kbase = kq * 128;

    __shared__ __align__(16) float As[2][16][128];
    __shared__ __align__(16) float Bs[2][16][128];

    const int tid = threadIdx.x;
    const int m0 = blockIdx.y * 128;
    const int j0 = blockIdx.x * 128;
    const int tx = tid & 15, ty = tid >> 4;
    const int mm = ty * 8, jj = tx * 8;
    const int lr = tid >> 5;
    const int lc = (tid & 31) * 4;

    unsigned long long acc[8][4];
#pragma unroll
    for (int i = 0; i < 8; i++)
#pragma unroll
        for (int j = 0; j < 4; j++) acc[i][j] = 0ULL;

    float4 ra0, ra1, rb0, rb1;
    ra0 = *(const float4*)(A + (kbase + lr) * 512 + m0 + lc);
    ra1 = *(const float4*)(A + (kbase + 8 + lr) * 512 + m0 + lc);
    rb0 = *(const float4*)(B + (kbase + lr) * 512 + j0 + lc);
    rb1 = *(const float4*)(B + (kbase + 8 + lr) * 512 + j0 + lc);
    *(float4*)&As[0][lr][lc] = ra0;
    *(float4*)&As[0][8 + lr][lc] = ra1;
    *(float4*)&Bs[0][lr][lc] = rb0;
    *(float4*)&Bs[0][8 + lr][lc] = rb1;
    __syncthreads();

    int buf = 0;
    for (int t = 0; t < 8; t++) {
        if (t < 7) {
            const int k0 = kbase + (t + 1) * 16;
            ra0 = *(const float4*)(A + (k0 + lr) * 512 + m0 + lc);
            ra1 = *(const float4*)(A + (k0 + 8 + lr) * 512 + m0 + lc);
            rb0 = *(const float4*)(B + (k0 + lr) * 512 + j0 + lc);
            rb1 = *(const float4*)(B + (k0 + 8 + lr) * 512 + j0 + lc);
        }
#pragma unroll
        for (int kk = 0; kk < 16; kk++) {
            const unsigned long long* bp = (const unsigned long long*)&Bs[buf][kk][jj];
            unsigned long long bv0 = bp[0], bv1 = bp[1], bv2 = bp[2], bv3 = bp[3];
#pragma unroll
            for (int i = 0; i < 8; i++) {
                unsigned long long av = bcast2(As[buf][kk][mm + i]);
                ffma2(acc[i][0], av, bv0);
                ffma2(acc[i][1], av, bv1);
                ffma2(acc[i][2], av, bv2);
                ffma2(acc[i][3], av, bv3);
            }
        }
        if (t < 7) {
            const int nb = buf ^ 1;
            *(float4*)&As[nb][lr][lc] = ra0;
            *(float4*)&As[nb][8 + lr][lc] = ra1;
            *(float4*)&Bs[nb][lr][lc] = rb0;
            *(float4*)&Bs[nb][8 + lr][lc] = rb1;
            __syncthreads();
            buf = nb;
        }
    }

#pragma unroll
    for (int i = 0; i < 8; i++) {
        float2* cp = (float2*)(C + (m0 + mm + i) * 512 + j0 + jj);
#pragma unroll
        for (int j = 0; j < 4; j++) cp[j] = unpk2(acc[i][j]);
    }
}

// ---------------- sum A^2 partials + bf16 split ------------------------------
__global__ void k_splitA2() {
    int idx = blockIdx.x * 256 + threadIdx.x;          // over 4 * 512 * 512
    if (idx >= 4 * NNODE * NNODE) return;
    int q = idx >> 18, o = idx & (NNODE * NNODE - 1);
    float v = (g_A2P[0][q][o] + g_A2P[1][q][o]) + (g_A2P[2][q][o] + g_A2P[3][q][o]);
    __nv_bfloat16 h = __float2bfloat16(v);
    g_ATh[4 + q][o] = h;
    g_ATl[4 + q][o] = __float2bfloat16(v - __bfloat162float(h));
}

// ---------------- W transpose + pad + bf16 split ----------------------------
__global__ void k_prepW(const float* __restrict__ W1, const float* __restrict__ W2) {
    const int z = blockIdx.y;
    const int BN = z ? 64 : 128;
    const float* __restrict__ W = z ? W2 : W1;
    __nv_bfloat16* __restrict__ dh = z ? g_W2h : g_W1h;
    __nv_bfloat16* __restrict__ dl = z ? g_W2l : g_W1l;
    int idx = blockIdx.x * 256 + threadIdx.x;
    if (idx >= KPAD * BN) return;
    int k = idx / BN, n = idx - k * BN;
    float v = (k < 462) ? W[k * BN + n] : 0.f;
    __nv_bfloat16 h = __float2bfloat16(v);
    dh[n * KPAD + k] = h;
    dl[n * KPAD + k] = __float2bfloat16(v - __bfloat162float(h));
}

// ---------------- fused source build: pack + transpose + split + H chunk 0 --
__global__ void k_src(int which, const float* __restrict__ inp,
                      const float* __restrict__ st) {
    __shared__ float t[32][33];
    const int jb = blockIdx.x * 32, nb = blockIdx.y * 32;
    const int tx = threadIdx.x & 31, ty = threadIdx.x >> 5;
#pragma unroll
    for (int r = 0; r < 32; r += 8) {
        const int n = nb + ty + r;
        const int j = jb + tx;
        const int b = j / CIN_, f = j - b * CIN_;
        float v;
        if (f < FIN_) {
            v = inp[(b * NNODE + n) * FIN_ + f];
        } else {
            const int c = f - FIN_;
            const float s = st[(b * NNODE + n) * COUT_ + c];
            v = which ? g_V[((size_t)n * BB + b) * 128 + c] * s : s;
        }
        t[ty + r][tx] = v;
        const size_t ho = ((size_t)n * BB + b) * KPAD + f;
        const __nv_bfloat16 h = __float2bfloat16(v);
        g_Hh[ho] = h;
        g_Hl[ho] = __float2bfloat16(v - __bfloat162float(h));
    }
    __syncthreads();
#pragma unroll
    for (int r = 0; r < 32; r += 8) {
        const float v = t[tx][ty + r];
        const __nv_bfloat16 h = __float2bfloat16(v);
        const size_t o = (size_t)(jb + ty + r) * NNODE + nb + tx;
        g_XTh[o] = h;
        g_XTl[o] = __float2bfloat16(v - __bfloat162float(h));
    }
}

// ---------------- diffusion GEMM on HMMA (BM=BN=128, BK=32, occ 2) ----------
// SW64 smem layout: row stride 64 B (32 bf16), atom 8 rows x 64 B.
#define OFF_AH 0
#define OFF_AL 8192
#define OFF_BH 16384
#define OFF_BL 24576
#define BUFSZ  32768
#define DIFF_SMEM (2 * BUFSZ)   // 65536 -> 2 CTAs/SM

__device__ __forceinline__ void diff_load(uint32_t sb, int buf,
                                          const __nv_bfloat16* Ah, const __nv_bfloat16* Al,
                                          int m0, int j0, int n0, int tid) {
    uint32_t base = sb + buf * BUFSZ;
#pragma unroll
    for (int i = 0; i < 2; i++) {
        int v = tid + i * 256;          // 0..511
        int row = v >> 2, ks = v & 3;   // 128 rows x 4 16B-granules
        uint32_t sw = SWZ64((uint32_t)(row * 64 + ks * 16));
        size_t goA = (size_t)(m0 + row) * NNODE + n0 + ks * 8;
        size_t goB = (size_t)(j0 + row) * NNODE + n0 + ks * 8;
        CP_ASYNC16(base + OFF_AH + sw, Ah + goA);
        CP_ASYNC16(base + OFF_AL + sw, Al + goA);
        CP_ASYNC16(base + OFF_BH + sw, g_XTh + goB);
        CP_ASYNC16(base + OFF_BL + sw, g_XTl + goB);
    }
}

// which: GCN index (0 -> adp1, 1 -> adp2). z: 0..5 = {A0,A1,adp,A0^2,A1^2,adp^2}
__global__ void __launch_bounds__(256, 2) k_diff_mma(int which) {
    extern __shared__ __align__(1024) char smem[];
    const uint32_t sb = smem_u32(smem);
    const int tid = threadIdx.x, wid = tid >> 5, lane = tid & 31;
    const int z = blockIdx.z;
    const int m0 = blockIdx.y * 128;
    const int j0 = blockIdx.x * 128;
    const int aIdx = (z == 0) ? 0 : (z == 1) ? 1 : (z == 2) ? (2 + which)
                   : (z == 3) ? 4 : (z == 4) ? 5 : (6 + which);
    const int ch = (z < 3) ? (1 + 2 * z) : (2 + 2 * (z - 3));

    const __nv_bfloat16* __restrict__ Ah = g_ATh[aIdx];
    const __nv_bfloat16* __restrict__ Al = g_ATl[aIdx];

    const int warp_m = wid & 3;
    const int warp_n = wid >> 2;

    float acc[2][8][4];
#pragma unroll
    for (int mi = 0; mi < 2; mi++)
#pragma unroll
        for (int ni = 0; ni < 8; ni++)
#pragma unroll
            for (int q = 0; q < 4; q++) acc[mi][ni][q] = 0.f;

    diff_load(sb, 0, Ah, Al, m0, j0, 0, tid);
    CP_COMMIT();

    for (int kt = 0; kt < 16; kt++) {
        if (kt < 15) {
            diff_load(sb, (kt + 1) & 1, Ah, Al, m0, j0, (kt + 1) * 32, tid);
            CP_COMMIT();
            CP_WAIT(1);
        } else {
            CP_WAIT(0);
        }
        __syncthreads();

        const uint32_t base = sb + (kt & 1) * BUFSZ;
#pragma unroll
        for (int kk = 0; kk < 2; kk++) {
            uint32_t ah[2][4], al[2][4];
#pragma unroll
            for (int mi = 0; mi < 2; mi++) {
                uint32_t off = (uint32_t)((warp_m * 32 + mi * 16 + (lane & 15)) * 64
                                          + kk * 32 + (lane >> 4) * 16);
                uint32_t sw = SWZ64(off);
                ldsm_x4(ah[mi], base + OFF_AH + sw);
                ldsm_x4(al[mi], base + OFF_AL + sw);
            }
            uint32_t bh[8][2], bl[8][2];
#pragma unroll
            for (int ni = 0; ni < 8; ni++) {
                uint32_t off = (uint32_t)((warp_n * 64 + ni * 8 + (lane & 7)) * 64
                                          + kk * 32 + ((lane >> 3) & 1) * 16);
                uint32_t sw = SWZ64(off);
                ldsm_x2(bh[ni], base + OFF_BH + sw);
                ldsm_x2(bl[ni], base + OFF_BL + sw);
            }
#pragma unroll
            for (int mi = 0; mi < 2; mi++)
#pragma unroll
                for (int ni = 0; ni < 8; ni++) {
                    mma16816(acc[mi][ni], ah[mi], bh[ni]);
                    mma16816(acc[mi][ni], ah[mi], bl[ni]);
                    mma16816(acc[mi][ni], al[mi], bh[ni]);
                }
        }
        __syncthreads();
    }

    // epilogue: write split H chunk
    const int g = lane >> 2, t = lane & 3;
#pragma unroll
    for (int mi = 0; mi < 2; mi++) {
        const int row = m0 + warp_m * 32 + mi * 16 + g;
#pragma unroll
        for (int ni = 0; ni < 8; ni++) {
            const int col = j0 + warp_n * 64 + ni * 8 + t * 2;   // always even
            const int b = col / CIN_, f = col - b * CIN_;
#pragma unroll
            for (int h2 = 0; h2 < 2; h2++) {
                const int rr = row + h2 * 8;
                const float vx = acc[mi][ni][h2 * 2 + 0];
                const float vy = acc[mi][ni][h2 * 2 + 1];
                const size_t ho = ((size_t)rr * BB + b) * KPAD + ch * CIN_ + f;
                __nv_bfloat162 hh = __floats2bfloat162_rn(vx, vy);
                *(__nv_bfloat162*)(g_Hh + ho) = hh;
                float lx = vx - __bfloat162float(hh.x);
                float ly = vy - __bfloat162float(hh.y);
                *(__nv_bfloat162*)(g_Hl + ho) = __floats2bfloat162_rn(lx, ly);
            }
        }
    }
}

// ---------------- output GEMM on HMMA (BK=32, occ 2) + fused epilogue -------
template <int BN, int ACT>
__global__ void __launch_bounds__(256, 2)
k_out_mma(const float* __restrict__ bias, const float* __restrict__ state,
          float* __restrict__ outp) {
    constexpr int NI = BN / 16;
    constexpr int ASZ = 8192;                // 128 rows x 32 bf16 x 2B
    constexpr int BSZ = BN * 32 * 2;
    constexpr int OAH = 0, OAL = ASZ, OBH = 2 * ASZ, OBL = 2 * ASZ + BSZ;
    constexpr int KBUF = 2 * ASZ + 2 * BSZ;

    extern __shared__ __align__(1024) char smem[];
    const uint32_t sb = smem_u32(smem);
    const int tid = threadIdx.x, wid = tid >> 5, lane = tid & 31;
    const int row0 = blockIdx.x * 128;

    const __nv_bfloat16* __restrict__ Wh = (BN == 128) ? g_W1h : g_W2h;
    const __nv_bfloat16* __restrict__ Wl = (BN == 128) ? g_W1l : g_W2l;

    const int warp_m = wid & 3;
    const int warp_n = wid >> 2;

    float acc[2][NI][4];
#pragma unroll
    for (int mi = 0; mi < 2; mi++)
#pragma unroll
        for (int ni = 0; ni < NI; ni++)
#pragma unroll
            for (int q = 0; q < 4; q++) acc[mi][ni][q] = 0.f;

    auto load_tile = [&](int buf, int k0) {
        uint32_t base = sb + buf * KBUF;
#pragma unroll
        for (int i = 0; i < 2; i++) {            // A: 512 chunks each h/l
            int v = tid + i * 256;
            int row = v >> 2, ks = v & 3;
            uint32_t sw = SWZ64((uint32_t)(row * 64 + ks * 16));
            size_t go = (size_t)(row0 + row) * KPAD + k0 + ks * 8;
            CP_ASYNC16(base + OAH + sw, g_Hh + go);
            CP_ASYNC16(base + OAL + sw, g_Hl + go);
        }
#pragma unroll
        for (int i = 0; i < BN * 4 / 256; i++) { // B: BN*4 chunks each h/l
            int v = tid + i * 256;
            int row = v >> 2, ks = v & 3;
            uint32_t sw = SWZ64((uint32_t)(row * 64 + ks * 16));
            size_t go = (size_t)row * KPAD + k0 + ks * 8;
            CP_ASYNC16(base + OBH + sw, Wh + go);
            CP_ASYNC16(base + OBL + sw, Wl + go);
        }
    };

    load_tile(0, 0);
    CP_COMMIT();

    for (int kt = 0; kt < 16; kt++) {
        if (kt < 15) {
            load_tile((kt + 1) & 1, (kt + 1) * 32);
            CP_COMMIT();
            CP_WAIT(1);
        } else {
            CP_WAIT(0);
        }
        __syncthreads();

        const uint32_t base = sb + (kt & 1) * KBUF;
#pragma unroll
        for (int kk = 0; kk < 2; kk++) {
            uint32_t ah[2][4], al[2][4];
#pragma unroll
            for (int mi = 0; mi < 2; mi++) {
                uint32_t off = (uint32_t)((warp_m * 32 + mi * 16 + (lane & 15)) * 64
                                          + kk * 32 + (lane >> 4) * 16);
                uint32_t sw = SWZ64(off);
                ldsm_x4(ah[mi], base + OAH + sw);
                ldsm_x4(al[mi], base + OAL + sw);
            }
            uint32_t bh[NI][2], bl[NI][2];
#pragma unroll
            for (int ni = 0; ni < NI; ni++) {
                uint32_t off = (uint32_t)((warp_n * (BN / 2) + ni * 8 + (lane & 7)) * 64
                                          + kk * 32 + ((lane >> 3) & 1) * 16);
                uint32_t sw = SWZ64(off);
                ldsm_x2(bh[ni], base + OBH + sw);
                ldsm_x2(bl[ni], base + OBL + sw);
            }
#pragma unroll
            for (int mi = 0; mi < 2; mi++)
#pragma unroll
                for (int ni = 0; ni < NI; ni++) {
                    mma16816(acc[mi][ni], ah[mi], bh[ni]);
                    mma16816(acc[mi][ni], ah[mi], bl[ni]);
                    mma16816(acc[mi][ni], al[mi], bh[ni]);
                }
        }
        __syncthreads();
    }

    // fused epilogue
    const int g = lane >> 2, t = lane & 3;
#pragma unroll
    for (int mi = 0; mi < 2; mi++) {
        const int row = row0 + warp_m * 32 + mi * 16 + g;
#pragma unroll
        for (int ni = 0; ni < NI; ni++) {
            const int col = warp_n * (BN / 2) + ni * 8 + t * 2;
            const float b0 = bias[col], b1 = bias[col + 1];
#pragma unroll
            for (int h2 = 0; h2 < 2; h2++) {
                const int rr = row + h2 * 8;
                const float vx = acc[mi][ni][h2 * 2 + 0] + b0;
                const float vy = acc[mi][ni][h2 * 2 + 1] + b1;
                if (ACT == 0) {
                    *(float2*)(g_V + (size_t)rr * 128 + col) =
                        make_float2(1.f / (1.f + __expf(-vx)),
                                    1.f / (1.f + __expf(-vy)));
                } else {
                    const int n = rr >> 7, b = rr & 127;
                    const float c0 = tanhf(vx), c1 = tanhf(vy);
                    const float u0 = g_V[(size_t)rr * 128 + 64 + col];
                    const float u1 = g_V[(size_t)rr * 128 + 64 + col + 1];
                    const size_t si = ((size_t)b * NNODE + n) * COUT_ + col;
                    const float st0 = state[si], st1 = state[si + 1];
                    *(float2*)(outp + si) =
                        make_float2(u0 * st0 + (1.f - u0) * c0,
                                    u1 * st1 + (1.f - u1) * c1);
                }
            }
        }
    }
}

// ---------------- launch ----------------------------------------------------
extern "C" void kernel_launch(void* const* d_in, const int* in_sizes, int n_in,
                              void* d_out, int out_size) {
    const float* input = (const float*)d_in[0];
    const float* state = (const float*)d_in[1];
    const float* A0    = (const float*)d_in[2];
    const float* A1    = (const float*)d_in[3];
    const float* nv1_1 = (const float*)d_in[4];
    const float* nv2_1 = (const float*)d_in[5];
    const float* W1    = (const float*)d_in[6];
    const float* b1    = (const float*)d_in[7];
    const float* nv1_2 = (const float*)d_in[8];
    const float* nv2_2 = (const float*)d_in[9];
    const float* W2    = (const float*)d_in[10];
    const float* b2    = (const float*)d_in[11];
    float* outp = (float*)d_out;

    constexpr int KO128_SMEM = 2 * (2 * 8192 + 2 * 8192);   // 65536
    constexpr int KO64_SMEM  = 2 * (2 * 8192 + 2 * 4096);   // 49152
    cudaFuncSetAttribute(k_diff_mma, cudaFuncAttributeMaxDynamicSharedMemorySize, DIFF_SMEM);
    cudaFuncSetAttribute(k_out_mma<128, 0>, cudaFuncAttributeMaxDynamicSharedMemorySize, KO128_SMEM);
    cudaFuncSetAttribute(k_out_mma<64, 1>,  cudaFuncAttributeMaxDynamicSharedMemorySize, KO64_SMEM);

    const dim3 gDiff(BF / 128, NNODE / 128, 6);      // (66, 4, 6)
    const dim3 gSrc(BF / 32, NNODE / 32);

    k_adp<<<dim3(NNODE, 2), 512>>>(nv1_1, nv2_1, nv1_2, nv2_2);
    k_prepA<<<dim3(16, 16, 4), 256>>>(A0, A1);
    k_prepW<<<dim3((KPAD * 128 + 255) / 256, 2), 256>>>(W1, W2);
    k_sq<<<dim3(4, 4, 16), 256>>>(A0, A1);
    k_splitA2<<<(4 * NNODE * NNODE + 255) / 256, 256>>>();

    // GCN 1
    k_src<<<gSrc, 256>>>(0, input, state);
    k_diff_mma<<<gDiff, 256, DIFF_SMEM>>>(0);
    k_out_mma<128, 0><<<NNODE * BB / 128, 256, KO128_SMEM>>>(b1, state, nullptr);

    // GCN 2
    k_src<<<gSrc, 256>>>(1, input, state);
    k_diff_mma<<<gDiff, 256, DIFF_SMEM>>>(1);
    k_out_mma<64, 1><<<NNODE * BB / 128, 256, KO64_SMEM>>>(b2, state, outp);
}

// round 15
// speedup vs baseline: 1.1752x; 1.0625x over previous
#include <cuda_runtime.h>
#include <cuda_bf16.h>
#include <cstdint>

#define BB     128
#define NNODE  512
#define FIN_   2
#define COUT_  64
#define CIN_   66
#define BF     8448     // BB * CIN_
#define KPAD   512      // padded concat-K (462 -> 512, zeros)

// ---------------- scratch (static device globals) ---------------------------
static __device__ float g_ADP[2][NNODE * NNODE];
static __device__ float g_V  [NNODE * BB * 128];
static __device__ __align__(16) float g_ATf[4][NNODE * NNODE];      // AT float (k_sq B-op)
static __device__ __align__(16) float g_A2P[4][4][NNODE * NNODE];   // A^2 K-quarter partials
// TILED split operands (16KB swizzled blocks): layout [mat][m_tile(4)][k_tile(8)][128x128B SWZ128]
// 0=A0T,1=A1T,2=adp1T,3=adp2T,4=A0^2T,5=A1^2T,6=adp1^2T,7=adp2^2T
static __device__ __align__(1024) __nv_bfloat16 g_ATh[8][NNODE * NNODE];
static __device__ __align__(1024) __nv_bfloat16 g_ATl[8][NNODE * NNODE];
// TILED XT: [j_tile(66)][k_tile(8)][128x128B SWZ128]
static __device__ __align__(1024) __nv_bfloat16 g_XTh[BF * NNODE];
static __device__ __align__(1024) __nv_bfloat16 g_XTl[BF * NNODE];
// pre-split concatenated H for the output GEMM: row = n*128+b, k = chunk*66+f
static __device__ __align__(16) __nv_bfloat16 g_Hh[(size_t)NNODE * BB * KPAD];
static __device__ __align__(16) __nv_bfloat16 g_Hl[(size_t)NNODE * BB * KPAD];
// transposed, padded, split weights: [n][KPAD]
static __device__ __align__(16) __nv_bfloat16 g_W1h[128 * KPAD];
static __device__ __align__(16) __nv_bfloat16 g_W1l[128 * KPAD];
static __device__ __align__(16) __nv_bfloat16 g_W2h[64 * KPAD];
static __device__ __align__(16) __nv_bfloat16 g_W2l[64 * KPAD];

// ---------------- PTX helpers -----------------------------------------------
__device__ __forceinline__ uint32_t smem_u32(const void* p) {
    uint32_t a;
    asm("{ .reg .u64 t; cvta.to.shared.u64 t, %1; cvt.u32.u64 %0, t; }" : "=r"(a) : "l"(p));
    return a;
}
#define SWZ128(off) ((off) ^ (((off) >> 3) & 0x70))
#define SWZ64(off)  ((off) ^ (((off) >> 3) & 0x30))

#define CP_ASYNC16(sm, gp) \
    asm volatile("cp.async.cg.shared.global [%0], [%1], 16;" :: "r"(sm), "l"(gp))
#define CP_COMMIT() asm volatile("cp.async.commit_group;" ::: "memory")
#define CP_WAIT(n)  asm volatile("cp.async.wait_group %0;" :: "n"(n) : "memory")

// 1D bulk async copy (sm_90 baseline) with mbarrier completion
#define CP_BULK(dst, src, bytes, mbar) \
    asm volatile("cp.async.bulk.shared::cluster.global.mbarrier::complete_tx::bytes " \
                 "[%0], [%1], %2, [%3];" \
                 :: "r"((uint32_t)(dst)), "l"(src), "r"((uint32_t)(bytes)), \
                    "r"((uint32_t)(mbar)) : "memory")

#define MBAR_INIT(mb, c)  asm volatile("mbarrier.init.shared.b64 [%0], %1;" :: "r"((uint32_t)(mb)), "r"((uint32_t)(c)) : "memory")
#define MBAR_INVAL(mb)    asm volatile("mbarrier.inval.shared.b64 [%0];" :: "r"((uint32_t)(mb)) : "memory")
#define MBAR_EXPECT_TX(mb, tx) \
    asm volatile("mbarrier.arrive.expect_tx.shared.b64 _, [%0], %1;" \
                 :: "r"((uint32_t)(mb)), "r"((uint32_t)(tx)) : "memory")

#define MBAR_WAIT(mb, ph) do {                                                    \
    uint32_t _m = (uint32_t)(mb), _p = (uint32_t)(ph), _d;                        \
    asm volatile("{\n\t.reg .pred p;\n\t"                                         \
        "mbarrier.try_wait.parity.acquire.cta.shared::cta.b64 p, [%1], %2;\n\t"   \
        "selp.b32 %0, 1, 0, p;\n\t}" : "=r"(_d) : "r"(_m), "r"(_p) : "memory");   \
    if (!_d) {                                                                    \
        asm volatile("{\n\t.reg .pred P1;\n\t"                                    \
            "WL_%=:\n\t"                                                          \
            "mbarrier.try_wait.parity.acquire.cta.shared::cta.b64 P1, [%0], %1, 0x989680;\n\t" \
            "@P1 bra.uni WD_%=;\n\t"                                              \
            "bra.uni WL_%=;\n\t"                                                  \
            "WD_%=:\n\t}" :: "r"(_m), "r"(_p) : "memory");                        \
    }                                                                             \
} while (0)

__device__ __forceinline__ void ldsm_x4(uint32_t* r, uint32_t addr) {
    asm volatile("ldmatrix.sync.aligned.m8n8.x4.shared.b16 {%0,%1,%2,%3}, [%4];"
                 : "=r"(r[0]), "=r"(r[1]), "=r"(r[2]), "=r"(r[3]) : "r"(addr));
}
__device__ __forceinline__ void ldsm_x2(uint32_t* r, uint32_t addr) {
    asm volatile("ldmatrix.sync.aligned.m8n8.x2.shared.b16 {%0,%1}, [%2];"
                 : "=r"(r[0]), "=r"(r[1]) : "r"(addr));
}
__device__ __forceinline__ void mma16816(float* c, const uint32_t* a, const uint32_t* b) {
    asm volatile("mma.sync.aligned.m16n8k16.row.col.f32.bf16.bf16.f32 "
                 "{%0,%1,%2,%3}, {%4,%5,%6,%7}, {%8,%9}, {%0,%1,%2,%3};"
                 : "+f"(c[0]), "+f"(c[1]), "+f"(c[2]), "+f"(c[3])
                 : "r"(a[0]), "r"(a[1]), "r"(a[2]), "r"(a[3]), "r"(b[0]), "r"(b[1]));
}

// ---------------- FFMA2 helpers (k_sq) --------------------------------------
__device__ __forceinline__ void ffma2(unsigned long long &d, unsigned long long a,
                                      unsigned long long b) {
    asm("fma.rn.f32x2 %0, %1, %2, %0;" : "+l"(d) : "l"(a), "l"(b));
}
__device__ __forceinline__ unsigned long long bcast2(float x) {
    unsigned long long r;
    asm("mov.b64 %0, {%1, %1};" : "=l"(r) : "f"(x));
    return r;
}
__device__ __forceinline__ float2 unpk2(unsigned long long v) {
    float lo, hi;
    asm("mov.b64 {%0, %1}, %2;" : "=f"(lo), "=f"(hi) : "l"(v));
    return make_float2(lo, hi);
}

// tiled byte offset inside a [rows x 64cols] split matrix stored as 16KB blocks
__device__ __forceinline__ size_t tile_off(int row, int col) {
    // row: full row index (M or J dim), col: full K index
    int rt = row >> 7, rr = row & 127;
    int kt = col >> 6, kc = col & 63;
    return ((size_t)rt * 8 + kt) * 16384 + SWZ128((uint32_t)(rr * 128 + kc * 2));
}

// ---------------- adaptive adjacency ----------------------------------------
__global__ void k_adp(const float* __restrict__ nv1a, const float* __restrict__ nv2a,
                      const float* __restrict__ nv1b, const float* __restrict__ nv2b) {
    const int which = blockIdx.y;
    const float* nv1 = which ? nv1b : nv1a;
    const float* nv2 = which ? nv2b : nv2a;
    const int n = blockIdx.x, m = threadIdx.x;
    float w[10];
#pragma unroll
    for (int t = 0; t < 10; t++) w[t] = nv1[n * 10 + t];
    float v = 0.f;
#pragma unroll
    for (int t = 0; t < 10; t++) v += w[t] * nv2[t * NNODE + m];
    v = fmaxf(v, 0.f);
    __shared__ float red[512];
    red[m] = v; __syncthreads();
    for (int s = 256; s > 0; s >>= 1) { if (m < s) red[m] = fmaxf(red[m], red[m + s]); __syncthreads(); }
    float mx = red[0]; __syncthreads();
    float e = __expf(v - mx);
    red[m] = e; __syncthreads();
    for (int s = 256; s > 0; s >>= 1) { if (m < s) red[m] += red[m + s]; __syncthreads(); }
    g_ADP[which][n * NNODE + m] = e / red[0];
}

// ---------------- A transpose + float AT + tiled bf16 split -----------------
__global__ void k_prepA(const float* __restrict__ A0, const float* __restrict__ A1) {
    const int a = blockIdx.z;
    const float* __restrict__ src = (a == 0) ? A0 : (a == 1) ? A1 : g_ADP[a - 2];
    __shared__ float t[32][33];
    const int mb = blockIdx.x * 32, nb = blockIdx.y * 32;
    const int tx = threadIdx.x & 31, ty = threadIdx.x >> 5;
#pragma unroll
    for (int r = 0; r < 32; r += 8)
        t[ty + r][tx] = src[(nb + ty + r) * NNODE + mb + tx];
    __syncthreads();
#pragma unroll
    for (int r = 0; r < 32; r += 8) {
        float v = t[tx][ty + r];                       // A[nb+tx][mb+ty+r]
        __nv_bfloat16 h = __float2bfloat16(v);
        float rem = v - __bfloat162float(h);
        int m = mb + ty + r, n = nb + tx;              // AT[m][n]
        g_ATf[a][m * NNODE + n] = v;
        size_t o = tile_off(m, n);
        *(__nv_bfloat16*)((char*)g_ATh[a] + o) = h;
        *(__nv_bfloat16*)((char*)g_ATl[a] + o) = __float2bfloat16(rem);
    }
}

// ---------------- A^2 partials (fp32 FFMA2, split-K=4) ----------------------
__global__ void __launch_bounds__(256, 2)
k_sq(const float* __restrict__ A0, const float* __restrict__ A1) {
    const int q = blockIdx.z >> 2;
    const int kq = blockIdx.z & 3;
    const float* __restrict__ A = (q == 0) ? A0 : (q == 1) ? A1 : g_ADP[q - 2];
    const float* __restrict__ B = g_ATf[q];
    float* __restrict__ C = g_A2P[kq][q];
    const int kbase = kq * 128;

    __shared__ __align__(16) float As[2][16][128];
    __shared__ __align__(16) float Bs[2][16][128];

    const int tid = threadIdx.x;
    const int m0 = blockIdx.y * 128;
    const int j0 = blockIdx.x * 128;
    const int tx = tid & 15, ty = tid >> 4;
    const int mm = ty * 8, jj = tx * 8;
    const int lr = tid >> 5;
    const int lc = (tid & 31) * 4;

    unsigned long long acc[8][4];
#pragma unroll
    for (int i = 0; i < 8; i++)
#pragma unroll
        for (int j = 0; j < 4; j++) acc[i][j] = 0ULL;

    float4 ra0, ra1, rb0, rb1;
    ra0 = *(const float4*)(A + (kbase + lr) * 512 + m0 + lc);
    ra1 = *(const float4*)(A + (kbase + 8 + lr) * 512 + m0 + lc);
    rb0 = *(const float4*)(B + (kbase + lr) * 512 + j0 + lc);
    rb1 = *(const float4*)(B + (kbase + 8 + lr) * 512 + j0 + lc);
    *(float4*)&As[0][lr][lc] = ra0;
    *(float4*)&As[0][8 + lr][lc] = ra1;
    *(float4*)&Bs[0][lr][lc] = rb0;
    *(float4*)&Bs[0][8 + lr][lc] = rb1;
    __syncthreads();

    int buf = 0;
    for (int t = 0; t < 8; t++) {
        if (t < 7) {
            const int k0 = kbase + (t + 1) * 16;
            ra0 = *(const float4*)(A + (k0 + lr) * 512 + m0 + lc);
            ra1 = *(const float4*)(A + (k0 + 8 + lr) * 512 + m0 + lc);
            rb0 = *(const float4*)(B + (k0 + lr) * 512 + j0 + lc);
            rb1 = *(const float4*)(B + (k0 + 8 + lr) * 512 + j0 + lc);
        }
#pragma unroll
        for (int kk = 0; kk < 16; kk++) {
            const unsigned long long* bp = (const unsigned long long*)&Bs[buf][kk][jj];
            unsigned long long bv0 = bp[0], bv1 = bp[1], bv2 = bp[2], bv3 = bp[3];
#pragma unroll
            for (int i = 0; i < 8; i++) {
                unsigned long long av = bcast2(As[buf][kk][mm + i]);
                ffma2(acc[i][0], av, bv0);
                ffma2(acc[i][1], av, bv1);
                ffma2(acc[i][2], av, bv2);
                ffma2(acc[i][3], av, bv3);
            }
        }
        if (t < 7) {
            const int nb = buf ^ 1;
            *(float4*)&As[nb][lr][lc] = ra0;
            *(float4*)&As[nb][8 + lr][lc] = ra1;
            *(float4*)&Bs[nb][lr][lc] = rb0;
            *(float4*)&Bs[nb][8 + lr][lc] = rb1;
            __syncthreads();
            buf = nb;
        }
    }

#pragma unroll
    for (int i = 0; i < 8; i++) {
        float2* cp = (float2*)(C + (m0 + mm + i) * 512 + j0 + jj);
#pragma unroll
        for (int j = 0; j < 4; j++) cp[j] = unpk2(acc[i][j]);
    }
}

// ---------------- sum A^2 partials + tiled bf16 split ------------------------
__global__ void k_splitA2() {
    int idx = blockIdx.x * 256 + threadIdx.x;          // over 4 * 512 * 512
    if (idx >= 4 * NNODE * NNODE) return;
    int q = idx >> 18, o = idx & (NNODE * NNODE - 1);
    int m = o >> 9, n = o & 511;
    float v = (g_A2P[0][q][o] + g_A2P[1][q][o]) + (g_A2P[2][q][o] + g_A2P[3][q][o]);
    __nv_bfloat16 h = __float2bfloat16(v);
    size_t to = tile_off(m, n);
    *(__nv_bfloat16*)((char*)g_ATh[4 + q] + to) = h;
    *(__nv_bfloat16*)((char*)g_ATl[4 + q] + to) = __float2bfloat16(v - __bfloat162float(h));
}

// ---------------- W transpose + pad + bf16 split ----------------------------
__global__ void k_prepW(const float* __restrict__ W1, const float* __restrict__ W2) {
    const int z = blockIdx.y;
    const int BN = z ? 64 : 128;
    const float* __restrict__ W = z ? W2 : W1;
    __nv_bfloat16* __restrict__ dh = z ? g_W2h : g_W1h;
    __nv_bfloat16* __restrict__ dl = z ? g_W2l : g_W1l;
    int idx = blockIdx.x * 256 + threadIdx.x;
    if (idx >= KPAD * BN) return;
    int k = idx / BN, n = idx - k * BN;
    float v = (k < 462) ? W[k * BN + n] : 0.f;
    __nv_bfloat16 h = __float2bfloat16(v);
    dh[n * KPAD + k] = h;
    dl[n * KPAD + k] = __float2bfloat16(v - __bfloat162float(h));
}

// ---------------- fused source build: pack + transpose + tiled split + H0 ---
__global__ void k_src(int which, const float* __restrict__ inp,
                      const float* __restrict__ st) {
    __shared__ float t[32][33];
    const int jb = blockIdx.x * 32, nb = blockIdx.y * 32;
    const int tx = threadIdx.x & 31, ty = threadIdx.x >> 5;
#pragma unroll
    for (int r = 0; r < 32; r += 8) {
        const int n = nb + ty + r;
        const int j = jb + tx;
        const int b = j / CIN_, f = j - b * CIN_;
        float v;
        if (f < FIN_) {
            v = inp[(b * NNODE + n) * FIN_ + f];
        } else {
            const int c = f - FIN_;
            const float s = st[(b * NNODE + n) * COUT_ + c];
            v = which ? g_V[((size_t)n * BB + b) * 128 + c] * s : s;
        }
        t[ty + r][tx] = v;
        const size_t ho = ((size_t)n * BB + b) * KPAD + f;
        const __nv_bfloat16 h = __float2bfloat16(v);
        g_Hh[ho] = h;
        g_Hl[ho] = __float2bfloat16(v - __bfloat162float(h));
    }
    __syncthreads();
#pragma unroll
    for (int r = 0; r < 32; r += 8) {
        const float v = t[tx][ty + r];
        const __nv_bfloat16 h = __float2bfloat16(v);
        const int j = jb + ty + r, n = nb + tx;        // XT[j][n]
        const size_t o = tile_off(j, n);
        *(__nv_bfloat16*)((char*)g_XTh + o) = h;
        *(__nv_bfloat16*)((char*)g_XTl + o) = __float2bfloat16(v - __bfloat162float(h));
    }
}

// ---------------- diffusion GEMM: cp.async.bulk + HMMA (BM=BN=128, BK=64) ---
#define OFF_AH 0
#define OFF_AL 16384
#define OFF_BH 32768
#define OFF_BL 49152
#define BUFSZ  65536
#define DIFF_SMEM (2 * BUFSZ)   // 131072

// which: GCN index (0 -> adp1, 1 -> adp2). z: 0..5 = {A0,A1,adp,A0^2,A1^2,adp^2}
__global__ void __launch_bounds__(256, 1) k_diff_mma(int which) {
    extern __shared__ __align__(1024) char smem[];
    __shared__ __align__(8) uint64_t mbarS[2];
    const uint32_t sb = smem_u32(smem);
    const uint32_t mb0 = smem_u32(&mbarS[0]);
    const uint32_t mb1 = smem_u32(&mbarS[1]);
    const int tid = threadIdx.x, wid = tid >> 5, lane = tid & 31;
    const int z = blockIdx.z;
    const int m0 = blockIdx.y * 128;
    const int j0 = blockIdx.x * 128;
    const int aIdx = (z == 0) ? 0 : (z == 1) ? 1 : (z == 2) ? (2 + which)
                   : (z == 3) ? 4 : (z == 4) ? 5 : (6 + which);
    const int ch = (z < 3) ? (1 + 2 * z) : (2 + 2 * (z - 3));

    // tiled chunk bases: 8 chunks of 16KB along K
    const char* AhB = (const char*)g_ATh[aIdx] + (size_t)blockIdx.y * 8 * 16384;
    const char* AlB = (const char*)g_ATl[aIdx] + (size_t)blockIdx.y * 8 * 16384;
    const char* BhB = (const char*)g_XTh + (size_t)blockIdx.x * 8 * 16384;
    const char* BlB = (const char*)g_XTl + (size_t)blockIdx.x * 8 * 16384;

    if (tid == 0) { MBAR_INIT(mb0, 1); MBAR_INIT(mb1, 1); }
    __syncthreads();

    const int warp_m = wid & 3;
    const int warp_n = wid >> 2;

    float acc[2][8][4];
#pragma unroll
    for (int mi = 0; mi < 2; mi++)
#pragma unroll
        for (int ni = 0; ni < 8; ni++)
#pragma unroll
            for (int q = 0; q < 4; q++) acc[mi][ni][q] = 0.f;

    if (tid == 0) {
        MBAR_EXPECT_TX(mb0, (uint32_t)BUFSZ);
        CP_BULK(sb + OFF_AH, AhB, 16384, mb0);
        CP_BULK(sb + OFF_AL, AlB, 16384, mb0);
        CP_BULK(sb + OFF_BH, BhB, 16384, mb0);
        CP_BULK(sb + OFF_BL, BlB, 16384, mb0);
    }

    for (int kt = 0; kt < 8; kt++) {
        const int b = kt & 1;
        if (kt < 7 && tid == 0) {
            const uint32_t mbn = (b ? mb0 : mb1);
            const uint32_t dst = sb + (b ^ 1) * BUFSZ;
            const size_t co = (size_t)(kt + 1) * 16384;
            MBAR_EXPECT_TX(mbn, (uint32_t)BUFSZ);
            CP_BULK(dst + OFF_AH, AhB + co, 16384, mbn);
            CP_BULK(dst + OFF_AL, AlB + co, 16384, mbn);
            CP_BULK(dst + OFF_BH, BhB + co, 16384, mbn);
            CP_BULK(dst + OFF_BL, BlB + co, 16384, mbn);
        }
        MBAR_WAIT(b ? mb1 : mb0, (kt >> 1) & 1);

        const uint32_t base = sb + b * BUFSZ;
#pragma unroll
        for (int kk = 0; kk < 4; kk++) {
            uint32_t ah[2][4], al[2][4];
#pragma unroll
            for (int mi = 0; mi < 2; mi++) {
                uint32_t off = (uint32_t)((warp_m * 32 + mi * 16 + (lane & 15)) * 128
                                          + kk * 32 + (lane >> 4) * 16);
                uint32_t sw = SWZ128(off);
                ldsm_x4(ah[mi], base + OFF_AH + sw);
                ldsm_x4(al[mi], base + OFF_AL + sw);
            }
            uint32_t bh[8][2], bl[8][2];
#pragma unroll
            for (int ni = 0; ni < 8; ni++) {
                uint32_t off = (uint32_t)((warp_n * 64 + ni * 8 + (lane & 7)) * 128
                                          + kk * 32 + ((lane >> 3) & 1) * 16);
                uint32_t sw = SWZ128(off);
                ldsm_x2(bh[ni], base + OFF_BH + sw);
                ldsm_x2(bl[ni], base + OFF_BL + sw);
            }
#pragma unroll
            for (int mi = 0; mi < 2; mi++)
#pragma unroll
                for (int ni = 0; ni < 8; ni++) {
                    mma16816(acc[mi][ni], ah[mi], bh[ni]);
                    mma16816(acc[mi][ni], ah[mi], bl[ni]);
                    mma16816(acc[mi][ni], al[mi], bh[ni]);
                }
        }
        __syncthreads();   // buffer b fully consumed; safe to refill at kt+2
    }

    if (tid == 0) { MBAR_INVAL(mb0); MBAR_INVAL(mb1); }

    // epilogue: write split H chunk
    const int g = lane >> 2, t = lane & 3;
#pragma unroll
    for (int mi = 0; mi < 2; mi++) {
        const int row = m0 + warp_m * 32 + mi * 16 + g;
#pragma unroll
        for (int ni = 0; ni < 8; ni++) {
            const int col = j0 + warp_n * 64 + ni * 8 + t * 2;   // always even
            const int b = col / CIN_, f = col - b * CIN_;
#pragma unroll
            for (int h2 = 0; h2 < 2; h2++) {
                const int rr = row + h2 * 8;
                const float vx = acc[mi][ni][h2 * 2 + 0];
                const float vy = acc[mi][ni][h2 * 2 + 1];
                const size_t ho = ((size_t)rr * BB + b) * KPAD + ch * CIN_ + f;
                __nv_bfloat162 hh = __floats2bfloat162_rn(vx, vy);
                *(__nv_bfloat162*)(g_Hh + ho) = hh;
                float lx = vx - __bfloat162float(hh.x);
                float ly = vy - __bfloat162float(hh.y);
                *(__nv_bfloat162*)(g_Hl + ho) = __floats2bfloat162_rn(lx, ly);
            }
        }
    }
}

// ---------------- output GEMM on HMMA (BK=32, occ 2) + fused epilogue -------
template <int BN, int ACT>
__global__ void __launch_bounds__(256, 2)
k_out_mma(const float* __restrict__ bias, const float* __restrict__ state,
          float* __restrict__ outp) {
    constexpr int NI = BN / 16;
    constexpr int ASZ = 8192;                // 128 rows x 32 bf16 x 2B
    constexpr int BSZ = BN * 32 * 2;
    constexpr int OAH = 0, OAL = ASZ, OBH = 2 * ASZ, OBL = 2 * ASZ + BSZ;
    constexpr int KBUF = 2 * ASZ + 2 * BSZ;

    extern __shared__ __align__(1024) char smem[];
    const uint32_t sb = smem_u32(smem);
    const int tid = threadIdx.x, wid = tid >> 5, lane = tid & 31;
    const int row0 = blockIdx.x * 128;

    const __nv_bfloat16* __restrict__ Wh = (BN == 128) ? g_W1h : g_W2h;
    const __nv_bfloat16* __restrict__ Wl = (BN == 128) ? g_W1l : g_W2l;

    const int warp_m = wid & 3;
    const int warp_n = wid >> 2;

    float acc[2][NI][4];
#pragma unroll
    for (int mi = 0; mi < 2; mi++)
#pragma unroll
        for (int ni = 0; ni < NI; ni++)
#pragma unroll
            for (int q = 0; q < 4; q++) acc[mi][ni][q] = 0.f;

    auto load_tile = [&](int buf, int k0) {
        uint32_t base = sb + buf * KBUF;
#pragma unroll
        for (int i = 0; i < 2; i++) {
            int v = tid + i * 256;
            int row = v >> 2, ks = v & 3;
            uint32_t sw = SWZ64((uint32_t)(row * 64 + ks * 16));
            size_t go = (size_t)(row0 + row) * KPAD + k0 + ks * 8;
            CP_ASYNC16(base + OAH + sw, g_Hh + go);
            CP_ASYNC16(base + OAL + sw, g_Hl + go);
        }
#pragma unroll
        for (int i = 0; i < BN * 4 / 256; i++) {
            int v = tid + i * 256;
            int row = v >> 2, ks = v & 3;
            uint32_t sw = SWZ64((uint32_t)(row * 64 + ks * 16));
            size_t go = (size_t)row * KPAD + k0 + ks * 8;
            CP_ASYNC16(base + OBH + sw, Wh + go);
            CP_ASYNC16(base + OBL + sw, Wl + go);
        }
    };

    load_tile(0, 0);
    CP_COMMIT();

    for (int kt = 0; kt < 16; kt++) {
        if (kt < 15) {
            load_tile((kt + 1) & 1, (kt + 1) * 32);
            CP_COMMIT();
            CP_WAIT(1);
        } else {
            CP_WAIT(0);
        }
        __syncthreads();

        const uint32_t base = sb + (kt & 1) * KBUF;
#pragma unroll
        for (int kk = 0; kk < 2; kk++) {
            uint32_t ah[2][4], al[2][4];
#pragma unroll
            for (int mi = 0; mi < 2; mi++) {
                uint32_t off = (uint32_t)((warp_m * 32 + mi * 16 + (lane & 15)) * 64
                                          + kk * 32 + (lane >> 4) * 16);
                uint32_t sw = SWZ64(off);
                ldsm_x4(ah[mi], base + OAH + sw);
                ldsm_x4(al[mi], base + OAL + sw);
            }
            uint32_t bh[NI][2], bl[NI][2];
#pragma unroll
            for (int ni = 0; ni < NI; ni++) {
                uint32_t off = (uint32_t)((warp_n * (BN / 2) + ni * 8 + (lane & 7)) * 64
                                          + kk * 32 + ((lane >> 3) & 1) * 16);
                uint32_t sw = SWZ64(off);
                ldsm_x2(bh[ni], base + OBH + sw);
                ldsm_x2(bl[ni], base + OBL + sw);
            }
#pragma unroll
            for (int mi = 0; mi < 2; mi++)
#pragma unroll
                for (int ni = 0; ni < NI; ni++) {
                    mma16816(acc[mi][ni], ah[mi], bh[ni]);
                    mma16816(acc[mi][ni], ah[mi], bl[ni]);
                    mma16816(acc[mi][ni], al[mi], bh[ni]);
                }
        }
        __syncthreads();
    }

    // fused epilogue
    const int g = lane >> 2, t = lane & 3;
#pragma unroll
    for (int mi = 0; mi < 2; mi++) {
        const int row = row0 + warp_m * 32 + mi * 16 + g;
#pragma unroll
        for (int ni = 0; ni < NI; ni++) {
            const int col = warp_n * (BN / 2) + ni * 8 + t * 2;
            const float b0 = bias[col], b1 = bias[col + 1];
#pragma unroll
            for (int h2 = 0; h2 < 2; h2++) {
                const int rr = row + h2 * 8;
                const float vx = acc[mi][ni][h2 * 2 + 0] + b0;
                const float vy = acc[mi][ni][h2 * 2 + 1] + b1;
                if (ACT == 0) {
                    *(float2*)(g_V + (size_t)rr * 128 + col) =
                        make_float2(1.f / (1.f + __expf(-vx)),
                                    1.f / (1.f + __expf(-vy)));
                } else {
                    const int n = rr >> 7, b = rr & 127;
                    const float c0 = tanhf(vx), c1 = tanhf(vy);
                    const float u0 = g_V[(size_t)rr * 128 + 64 + col];
                    const float u1 = g_V[(size_t)rr * 128 + 64 + col + 1];
                    const size_t si = ((size_t)b * NNODE + n) * COUT_ + col;
                    const float st0 = state[si], st1 = state[si + 1];
                    *(float2*)(outp + si) =
                        make_float2(u0 * st0 + (1.f - u0) * c0,
                                    u1 * st1 + (1.f - u1) * c1);
                }
            }
        }
    }
}

// ---------------- launch ----------------------------------------------------
extern "C" void kernel_launch(void* const* d_in, const int* in_sizes, int n_in,
                              void* d_out, int out_size) {
    const float* input = (const float*)d_in[0];
    const float* state = (const float*)d_in[1];
    const float* A0    = (const float*)d_in[2];
    const float* A1    = (const float*)d_in[3];
    const float* nv1_1 = (const float*)d_in[4];
    const float* nv2_1 = (const float*)d_in[5];
    const float* W1    = (const float*)d_in[6];
    const float* b1    = (const float*)d_in[7];
    const float* nv1_2 = (const float*)d_in[8];
    const float* nv2_2 = (const float*)d_in[9];
    const float* W2    = (const float*)d_in[10];
    const float* b2    = (const float*)d_in[11];
    float* outp = (float*)d_out;

    constexpr int KO128_SMEM = 2 * (2 * 8192 + 2 * 8192);   // 65536
    constexpr int KO64_SMEM  = 2 * (2 * 8192 + 2 * 4096);   // 49152
    cudaFuncSetAttribute(k_diff_mma, cudaFuncAttributeMaxDynamicSharedMemorySize, DIFF_SMEM);
    cudaFuncSetAttribute(k_out_mma<128, 0>, cudaFuncAttributeMaxDynamicSharedMemorySize, KO128_SMEM);
    cudaFuncSetAttribute(k_out_mma<64, 1>,  cudaFuncAttributeMaxDynamicSharedMemorySize, KO64_SMEM);

    const dim3 gDiff(BF / 128, NNODE / 128, 6);      // (66, 4, 6)
    const dim3 gSrc(BF / 32, NNODE / 32);

    k_adp<<<dim3(NNODE, 2), 512>>>(nv1_1, nv2_1, nv1_2, nv2_2);
    k_prepA<<<dim3(16, 16, 4), 256>>>(A0, A1);
    k_prepW<<<dim3((KPAD * 128 + 255) / 256, 2), 256>>>(W1, W2);
    k_sq<<<dim3(4, 4, 16), 256>>>(A0, A1);
    k_splitA2<<<(4 * NNODE * NNODE + 255) / 256, 256>>>();

    // GCN 1
    k_src<<<gSrc, 256>>>(0, input, state);
    k_diff_mma<<<gDiff, 256, DIFF_SMEM>>>(0);
    k_out_mma<128, 0><<<NNODE * BB / 128, 256, KO128_SMEM>>>(b1, state, nullptr);

    // GCN 2
    k_src<<<gSrc, 256>>>(1, input, state);
    k_diff_mma<<<gDiff, 256, DIFF_SMEM>>>(1);
    k_out_mma<64, 1><<<NNODE * BB / 128, 256, KO64_SMEM>>>(b2, state, outp);
}

// round 16
// speedup vs baseline: 1.2763x; 1.0860x over previous
#include <cuda_runtime.h>
#include <cuda_bf16.h>
#include <cstdint>

#define BB     128
#define NNODE  512
#define FIN_   2
#define COUT_  64
#define CIN_   66
#define BF     8448     // BB * CIN_
#define KPAD   512      // padded concat-K (462 -> 512, zeros)

// ---------------- scratch (static device globals) ---------------------------
static __device__ float g_ADP[2][NNODE * NNODE];
static __device__ float g_V  [NNODE * BB * 128];
static __device__ __align__(16) float g_ATf[4][NNODE * NNODE];      // AT float (k_sq B-op)
static __device__ __align__(16) float g_A2P[4][4][NNODE * NNODE];   // A^2 K-quarter partials
// TILED split operands (8KB SWZ64 blocks): [mat][m_tile(4)][k_tile(16)][128 rows x 32 cols]
// 0=A0T,1=A1T,2=adp1T,3=adp2T,4=A0^2T,5=A1^2T,6=adp1^2T,7=adp2^2T
static __device__ __align__(1024) __nv_bfloat16 g_ATh[8][NNODE * NNODE];
static __device__ __align__(1024) __nv_bfloat16 g_ATl[8][NNODE * NNODE];
// TILED XT: [j_tile(66)][k_tile(16)][128 rows x 32 cols SWZ64]
static __device__ __align__(1024) __nv_bfloat16 g_XTh[BF * NNODE];
static __device__ __align__(1024) __nv_bfloat16 g_XTl[BF * NNODE];
// pre-split concatenated H for the output GEMM: row = n*128+b, k = chunk*66+f
static __device__ __align__(16) __nv_bfloat16 g_Hh[(size_t)NNODE * BB * KPAD];
static __device__ __align__(16) __nv_bfloat16 g_Hl[(size_t)NNODE * BB * KPAD];
// transposed, padded, split weights: [n][KPAD]
static __device__ __align__(16) __nv_bfloat16 g_W1h[128 * KPAD];
static __device__ __align__(16) __nv_bfloat16 g_W1l[128 * KPAD];
static __device__ __align__(16) __nv_bfloat16 g_W2h[64 * KPAD];
static __device__ __align__(16) __nv_bfloat16 g_W2l[64 * KPAD];

// ---------------- PTX helpers -----------------------------------------------
__device__ __forceinline__ uint32_t smem_u32(const void* p) {
    uint32_t a;
    asm("{ .reg .u64 t; cvta.to.shared.u64 t, %1; cvt.u32.u64 %0, t; }" : "=r"(a) : "l"(p));
    return a;
}
#define SWZ64(off)  ((off) ^ (((off) >> 3) & 0x30))

#define CP_ASYNC16(sm, gp) \
    asm volatile("cp.async.cg.shared.global [%0], [%1], 16;" :: "r"(sm), "l"(gp))
#define CP_COMMIT() asm volatile("cp.async.commit_group;" ::: "memory")
#define CP_WAIT(n)  asm volatile("cp.async.wait_group %0;" :: "n"(n) : "memory")

// 1D bulk async copy with mbarrier completion
#define CP_BULK(dst, src, bytes, mbar) \
    asm volatile("cp.async.bulk.shared::cluster.global.mbarrier::complete_tx::bytes " \
                 "[%0], [%1], %2, [%3];" \
                 :: "r"((uint32_t)(dst)), "l"(src), "r"((uint32_t)(bytes)), \
                    "r"((uint32_t)(mbar)) : "memory")

#define MBAR_INIT(mb, c)  asm volatile("mbarrier.init.shared.b64 [%0], %1;" :: "r"((uint32_t)(mb)), "r"((uint32_t)(c)) : "memory")
#define MBAR_INVAL(mb)    asm volatile("mbarrier.inval.shared.b64 [%0];" :: "r"((uint32_t)(mb)) : "memory")
#define MBAR_EXPECT_TX(mb, tx) \
    asm volatile("mbarrier.arrive.expect_tx.shared.b64 _, [%0], %1;" \
                 :: "r"((uint32_t)(mb)), "r"((uint32_t)(tx)) : "memory")

#define MBAR_WAIT(mb, ph) do {                                                    \
    uint32_t _m = (uint32_t)(mb), _p = (uint32_t)(ph), _d;                        \
    asm volatile("{\n\t.reg .pred p;\n\t"                                         \
        "mbarrier.try_wait.parity.acquire.cta.shared::cta.b64 p, [%1], %2;\n\t"   \
        "selp.b32 %0, 1, 0, p;\n\t}" : "=r"(_d) : "r"(_m), "r"(_p) : "memory");   \
    if (!_d) {                                                                    \
        asm volatile("{\n\t.reg .pred P1;\n\t"                                    \
            "WL_%=:\n\t"                                                          \
            "mbarrier.try_wait.parity.acquire.cta.shared::cta.b64 P1, [%0], %1, 0x989680;\n\t" \
            "@P1 bra.uni WD_%=;\n\t"                                              \
            "bra.uni WL_%=;\n\t"                                                  \
            "WD_%=:\n\t}" :: "r"(_m), "r"(_p) : "memory");                        \
    }                                                                             \
} while (0)

__device__ __forceinline__ void ldsm_x4(uint32_t* r, uint32_t addr) {
    asm volatile("ldmatrix.sync.aligned.m8n8.x4.shared.b16 {%0,%1,%2,%3}, [%4];"
                 : "=r"(r[0]), "=r"(r[1]), "=r"(r[2]), "=r"(r[3]) : "r"(addr));
}
__device__ __forceinline__ void ldsm_x2(uint32_t* r, uint32_t addr) {
    asm volatile("ldmatrix.sync.aligned.m8n8.x2.shared.b16 {%0,%1}, [%2];"
                 : "=r"(r[0]), "=r"(r[1]) : "r"(addr));
}
__device__ __forceinline__ void mma16816(float* c, const uint32_t* a, const uint32_t* b) {
    asm volatile("mma.sync.aligned.m16n8k16.row.col.f32.bf16.bf16.f32 "
                 "{%0,%1,%2,%3}, {%4,%5,%6,%7}, {%8,%9}, {%0,%1,%2,%3};"
                 : "+f"(c[0]), "+f"(c[1]), "+f"(c[2]), "+f"(c[3])
                 : "r"(a[0]), "r"(a[1]), "r"(a[2]), "r"(a[3]), "r"(b[0]), "r"(b[1]));
}

// ---------------- FFMA2 helpers (k_sq) --------------------------------------
__device__ __forceinline__ void ffma2(unsigned long long &d, unsigned long long a,
                                      unsigned long long b) {
    asm("fma.rn.f32x2 %0, %1, %2, %0;" : "+l"(d) : "l"(a), "l"(b));
}
__device__ __forceinline__ unsigned long long bcast2(float x) {
    unsigned long long r;
    asm("mov.b64 %0, {%1, %1};" : "=l"(r) : "f"(x));
    return r;
}
__device__ __forceinline__ float2 unpk2(unsigned long long v) {
    float lo, hi;
    asm("mov.b64 {%0, %1}, %2;" : "=f"(lo), "=f"(hi) : "l"(v));
    return make_float2(lo, hi);
}

// tiled byte offset: [rows][K] matrix stored as 8KB blocks of [128 rows x 32 cols], SWZ64
__device__ __forceinline__ size_t tile_off(int row, int col) {
    int rt = row >> 7, rr = row & 127;
    int kt = col >> 5, kc = col & 31;
    return ((size_t)rt * 16 + kt) * 8192 + SWZ64((uint32_t)(rr * 64 + kc * 2));
}

// ---------------- adaptive adjacency ----------------------------------------
__global__ void k_adp(const float* __restrict__ nv1a, const float* __restrict__ nv2a,
                      const float* __restrict__ nv1b, const float* __restrict__ nv2b) {
    const int which = blockIdx.y;
    const float* nv1 = which ? nv1b : nv1a;
    const float* nv2 = which ? nv2b : nv2a;
    const int n = blockIdx.x, m = threadIdx.x;
    float w[10];
#pragma unroll
    for (int t = 0; t < 10; t++) w[t] = nv1[n * 10 + t];
    float v = 0.f;
#pragma unroll
    for (int t = 0; t < 10; t++) v += w[t] * nv2[t * NNODE + m];
    v = fmaxf(v, 0.f);
    __shared__ float red[512];
    red[m] = v; __syncthreads();
    for (int s = 256; s > 0; s >>= 1) { if (m < s) red[m] = fmaxf(red[m], red[m + s]); __syncthreads(); }
    float mx = red[0]; __syncthreads();
    float e = __expf(v - mx);
    red[m] = e; __syncthreads();
    for (int s = 256; s > 0; s >>= 1) { if (m < s) red[m] += red[m + s]; __syncthreads(); }
    g_ADP[which][n * NNODE + m] = e / red[0];
}

// ---------------- A transpose + float AT + tiled bf16 split -----------------
__global__ void k_prepA(const float* __restrict__ A0, const float* __restrict__ A1) {
    const int a = blockIdx.z;
    const float* __restrict__ src = (a == 0) ? A0 : (a == 1) ? A1 : g_ADP[a - 2];
    __shared__ float t[32][33];
    const int mb = blockIdx.x * 32, nb = blockIdx.y * 32;
    const int tx = threadIdx.x & 31, ty = threadIdx.x >> 5;
#pragma unroll
    for (int r = 0; r < 32; r += 8)
        t[ty + r][tx] = src[(nb + ty + r) * NNODE + mb + tx];
    __syncthreads();
#pragma unroll
    for (int r = 0; r < 32; r += 8) {
        float v = t[tx][ty + r];                       // A[nb+tx][mb+ty+r]
        __nv_bfloat16 h = __float2bfloat16(v);
        float rem = v - __bfloat162float(h);
        int m = mb + ty + r, n = nb + tx;              // AT[m][n]
        g_ATf[a][m * NNODE + n] = v;
        size_t o = tile_off(m, n);
        *(__nv_bfloat16*)((char*)g_ATh[a] + o) = h;
        *(__nv_bfloat16*)((char*)g_ATl[a] + o) = __float2bfloat16(rem);
    }
}

// ---------------- A^2 partials (fp32 FFMA2, split-K=4) ----------------------
__global__ void __launch_bounds__(256, 2)
k_sq(const float* __restrict__ A0, const float* __restrict__ A1) {
    const int q = blockIdx.z >> 2;
    const int kq = blockIdx.z & 3;
    const float* __restrict__ A = (q == 0) ? A0 : (q == 1) ? A1 : g_ADP[q - 2];
    const float* __restrict__ B = g_ATf[q];
    float* __restrict__ C = g_A2P[kq][q];
    const int kbase = kq * 128;

    __shared__ __align__(16) float As[2][16][128];
    __shared__ __align__(16) float Bs[2][16][128];

    const int tid = threadIdx.x;
    const int m0 = blockIdx.y * 128;
    const int j0 = blockIdx.x * 128;
    const int tx = tid & 15, ty = tid >> 4;
    const int mm = ty * 8, jj = tx * 8;
    const int lr = tid >> 5;
    const int lc = (tid & 31) * 4;

    unsigned long long acc[8][4];
#pragma unroll
    for (int i = 0; i < 8; i++)
#pragma unroll
        for (int j = 0; j < 4; j++) acc[i][j] = 0ULL;

    float4 ra0, ra1, rb0, rb1;
    ra0 = *(const float4*)(A + (kbase + lr) * 512 + m0 + lc);
    ra1 = *(const float4*)(A + (kbase + 8 + lr) * 512 + m0 + lc);
    rb0 = *(const float4*)(B + (kbase + lr) * 512 + j0 + lc);
    rb1 = *(const float4*)(B + (kbase + 8 + lr) * 512 + j0 + lc);
    *(float4*)&As[0][lr][lc] = ra0;
    *(float4*)&As[0][8 + lr][lc] = ra1;
    *(float4*)&Bs[0][lr][lc] = rb0;
    *(float4*)&Bs[0][8 + lr][lc] = rb1;
    __syncthreads();

    int buf = 0;
    for (int t = 0; t < 8; t++) {
        if (t < 7) {
            const int k0 = kbase + (t + 1) * 16;
            ra0 = *(const float4*)(A + (k0 + lr) * 512 + m0 + lc);
            ra1 = *(const float4*)(A + (k0 + 8 + lr) * 512 + m0 + lc);
            rb0 = *(const float4*)(B + (k0 + lr) * 512 + j0 + lc);
            rb1 = *(const float4*)(B + (k0 + 8 + lr) * 512 + j0 + lc);
        }
#pragma unroll
        for (int kk = 0; kk < 16; kk++) {
            const unsigned long long* bp = (const unsigned long long*)&Bs[buf][kk][jj];
            unsigned long long bv0 = bp[0], bv1 = bp[1], bv2 = bp[2], bv3 = bp[3];
#pragma unroll
            for (int i = 0; i < 8; i++) {
                unsigned long long av = bcast2(As[buf][kk][mm + i]);
                ffma2(acc[i][0], av, bv0);
                ffma2(acc[i][1], av, bv1);
                ffma2(acc[i][2], av, bv2);
                ffma2(acc[i][3], av, bv3);
            }
        }
        if (t < 7) {
            const int nb = buf ^ 1;
            *(float4*)&As[nb][lr][lc] = ra0;
            *(float4*)&As[nb][8 + lr][lc] = ra1;
            *(float4*)&Bs[nb][lr][lc] = rb0;
            *(float4*)&Bs[nb][8 + lr][lc] = rb1;
            __syncthreads();
            buf = nb;
        }
    }

#pragma unroll
    for (int i = 0; i < 8; i++) {
        float2* cp = (float2*)(C + (m0 + mm + i) * 512 + j0 + jj);
#pragma unroll
        for (int j = 0; j < 4; j++) cp[j] = unpk2(acc[i][j]);
    }
}

// ---------------- sum A^2 partials + tiled bf16 split ------------------------
__global__ void k_splitA2() {
    int idx = blockIdx.x * 256 + threadIdx.x;          // over 4 * 512 * 512
    if (idx >= 4 * NNODE * NNODE) return;
    int q = idx >> 18, o = idx & (NNODE * NNODE - 1);
    int m = o >> 9, n = o & 511;
    float v = (g_A2P[0][q][o] + g_A2P[1][q][o]) + (g_A2P[2][q][o] + g_A2P[3][q][o]);
    __nv_bfloat16 h = __float2bfloat16(v);
    size_t to = tile_off(m, n);
    *(__nv_bfloat16*)((char*)g_ATh[4 + q] + to) = h;
    *(__nv_bfloat16*)((char*)g_ATl[4 + q] + to) = __float2bfloat16(v - __bfloat162float(h));
}

// ---------------- W transpose + pad + bf16 split ----------------------------
__global__ void k_prepW(const float* __restrict__ W1, const float* __restrict__ W2) {
    const int z = blockIdx.y;
    const int BN = z ? 64 : 128;
    const float* __restrict__ W = z ? W2 : W1;
    __nv_bfloat16* __restrict__ dh = z ? g_W2h : g_W1h;
    __nv_bfloat16* __restrict__ dl = z ? g_W2l : g_W1l;
    int idx = blockIdx.x * 256 + threadIdx.x;
    if (idx >= KPAD * BN) return;
    int k = idx / BN, n = idx - k * BN;
    float v = (k < 462) ? W[k * BN + n] : 0.f;
    __nv_bfloat16 h = __float2bfloat16(v);
    dh[n * KPAD + k] = h;
    dl[n * KPAD + k] = __float2bfloat16(v - __bfloat162float(h));
}

// ---------------- fused source build: pack + transpose + tiled split + H0 ---
__global__ void k_src(int which, const float* __restrict__ inp,
                      const float* __restrict__ st) {
    __shared__ float t[32][33];
    const int jb = blockIdx.x * 32, nb = blockIdx.y * 32;
    const int tx = threadIdx.x & 31, ty = threadIdx.x >> 5;
#pragma unroll
    for (int r = 0; r < 32; r += 8) {
        const int n = nb + ty + r;
        const int j = jb + tx;
        const int b = j / CIN_, f = j - b * CIN_;
        float v;
        if (f < FIN_) {
            v = inp[(b * NNODE + n) * FIN_ + f];
        } else {
            const int c = f - FIN_;
            const float s = st[(b * NNODE + n) * COUT_ + c];
            v = which ? g_V[((size_t)n * BB + b) * 128 + c] * s : s;
        }
        t[ty + r][tx] = v;
        const size_t ho = ((size_t)n * BB + b) * KPAD + f;
        const __nv_bfloat16 h = __float2bfloat16(v);
        g_Hh[ho] = h;
        g_Hl[ho] = __float2bfloat16(v - __bfloat162float(h));
    }
    __syncthreads();
#pragma unroll
    for (int r = 0; r < 32; r += 8) {
        const float v = t[tx][ty + r];
        const __nv_bfloat16 h = __float2bfloat16(v);
        const int j = jb + ty + r, n = nb + tx;        // XT[j][n]
        const size_t o = tile_off(j, n);
        *(__nv_bfloat16*)((char*)g_XTh + o) = h;
        *(__nv_bfloat16*)((char*)g_XTl + o) = __float2bfloat16(v - __bfloat162float(h));
    }
}

// ---------------- diffusion GEMM: cp.async.bulk + HMMA (BK=32, occ 2) -------
#define OFF_AH 0
#define OFF_AL 8192
#define OFF_BH 16384
#define OFF_BL 24576
#define BUFSZ  32768
#define DIFF_SMEM (2 * BUFSZ)   // 65536 -> 2 CTAs/SM

// which: GCN index (0 -> adp1, 1 -> adp2). z: 0..5 = {A0,A1,adp,A0^2,A1^2,adp^2}
__global__ void __launch_bounds__(256, 2) k_diff_mma(int which) {
    extern __shared__ __align__(1024) char smem[];
    __shared__ __align__(8) uint64_t mbarS[2];
    const uint32_t sb = smem_u32(smem);
    const uint32_t mb0 = smem_u32(&mbarS[0]);
    const uint32_t mb1 = smem_u32(&mbarS[1]);
    const int tid = threadIdx.x, wid = tid >> 5, lane = tid & 31;
    const int z = blockIdx.z;
    const int m0 = blockIdx.y * 128;
    const int j0 = blockIdx.x * 128;
    const int aIdx = (z == 0) ? 0 : (z == 1) ? 1 : (z == 2) ? (2 + which)
                   : (z == 3) ? 4 : (z == 4) ? 5 : (6 + which);
    const int ch = (z < 3) ? (1 + 2 * z) : (2 + 2 * (z - 3));

    // tiled chunk bases: 16 chunks of 8KB along K
    const char* AhB = (const char*)g_ATh[aIdx] + (size_t)blockIdx.y * 16 * 8192;
    const char* AlB = (const char*)g_ATl[aIdx] + (size_t)blockIdx.y * 16 * 8192;
    const char* BhB = (const char*)g_XTh + (size_t)blockIdx.x * 16 * 8192;
    const char* BlB = (const char*)g_XTl + (size_t)blockIdx.x * 16 * 8192;

    if (tid == 0) { MBAR_INIT(mb0, 1); MBAR_INIT(mb1, 1); }
    __syncthreads();

    const int warp_m = wid & 3;
    const int warp_n = wid >> 2;

    float acc[2][8][4];
#pragma unroll
    for (int mi = 0; mi < 2; mi++)
#pragma unroll
        for (int ni = 0; ni < 8; ni++)
#pragma unroll
            for (int q = 0; q < 4; q++) acc[mi][ni][q] = 0.f;

    if (tid == 0) {
        MBAR_EXPECT_TX(mb0, (uint32_t)BUFSZ);
        CP_BULK(sb + OFF_AH, AhB, 8192, mb0);
        CP_BULK(sb + OFF_AL, AlB, 8192, mb0);
        CP_BULK(sb + OFF_BH, BhB, 8192, mb0);
        CP_BULK(sb + OFF_BL, BlB, 8192, mb0);
    }

    for (int kt = 0; kt < 16; kt++) {
        const int b = kt & 1;
        if (kt < 15 && tid == 0) {
            const uint32_t mbn = (b ? mb0 : mb1);
            const uint32_t dst = sb + (b ^ 1) * BUFSZ;
            const size_t co = (size_t)(kt + 1) * 8192;
            MBAR_EXPECT_TX(mbn, (uint32_t)BUFSZ);
            CP_BULK(dst + OFF_AH, AhB + co, 8192, mbn);
            CP_BULK(dst + OFF_AL, AlB + co, 8192, mbn);
            CP_BULK(dst + OFF_BH, BhB + co, 8192, mbn);
            CP_BULK(dst + OFF_BL, BlB + co, 8192, mbn);
        }
        MBAR_WAIT(b ? mb1 : mb0, (kt >> 1) & 1);

        const uint32_t base = sb + b * BUFSZ;
#pragma unroll
        for (int kk = 0; kk < 2; kk++) {
            uint32_t ah[2][4], al[2][4];
#pragma unroll
            for (int mi = 0; mi < 2; mi++) {
                uint32_t off = (uint32_t)((warp_m * 32 + mi * 16 + (lane & 15)) * 64
                                          + kk * 32 + (lane >> 4) * 16);
                uint32_t sw = SWZ64(off);
                ldsm_x4(ah[mi], base + OFF_AH + sw);
                ldsm_x4(al[mi], base + OFF_AL + sw);
            }
            uint32_t bh[8][2], bl[8][2];
#pragma unroll
            for (int ni = 0; ni < 8; ni++) {
                uint32_t off = (uint32_t)((warp_n * 64 + ni * 8 + (lane & 7)) * 64
                                          + kk * 32 + ((lane >> 3) & 1) * 16);
                uint32_t sw = SWZ64(off);
                ldsm_x2(bh[ni], base + OFF_BH + sw);
                ldsm_x2(bl[ni], base + OFF_BL + sw);
            }
#pragma unroll
            for (int mi = 0; mi < 2; mi++)
#pragma unroll
                for (int ni = 0; ni < 8; ni++) {
                    mma16816(acc[mi][ni], ah[mi], bh[ni]);
                    mma16816(acc[mi][ni], ah[mi], bl[ni]);
                    mma16816(acc[mi][ni], al[mi], bh[ni]);
                }
        }
        __syncthreads();   // buffer b consumed; safe to refill at kt+2
    }

    if (tid == 0) { MBAR_INVAL(mb0); MBAR_INVAL(mb1); }

    // epilogue: write split H chunk
    const int g = lane >> 2, t = lane & 3;
#pragma unroll
    for (int mi = 0; mi < 2; mi++) {
        const int row = m0 + warp_m * 32 + mi * 16 + g;
#pragma unroll
        for (int ni = 0; ni < 8; ni++) {
            const int col = j0 + warp_n * 64 + ni * 8 + t * 2;   // always even
            const int b = col / CIN_, f = col - b * CIN_;
#pragma unroll
            for (int h2 = 0; h2 < 2; h2++) {
                const int rr = row + h2 * 8;
                const float vx = acc[mi][ni][h2 * 2 + 0];
                const float vy = acc[mi][ni][h2 * 2 + 1];
                const size_t ho = ((size_t)rr * BB + b) * KPAD + ch * CIN_ + f;
                __nv_bfloat162 hh = __floats2bfloat162_rn(vx, vy);
                *(__nv_bfloat162*)(g_Hh + ho) = hh;
                float lx = vx - __bfloat162float(hh.x);
                float ly = vy - __bfloat162float(hh.y);
                *(__nv_bfloat162*)(g_Hl + ho) = __floats2bfloat162_rn(lx, ly);
            }
        }
    }
}

// ---------------- output GEMM on HMMA (BK=32, occ 2) + fused epilogue -------
template <int BN, int ACT>
__global__ void __launch_bounds__(256, 2)
k_out_mma(const float* __restrict__ bias, const float* __restrict__ state,
          float* __restrict__ outp) {
    constexpr int NI = BN / 16;
    constexpr int ASZ = 8192;                // 128 rows x 32 bf16 x 2B
    constexpr int BSZ = BN * 32 * 2;
    constexpr int OAH = 0, OAL = ASZ, OBH = 2 * ASZ, OBL = 2 * ASZ + BSZ;
    constexpr int KBUF = 2 * ASZ + 2 * BSZ;

    extern __shared__ __align__(1024) char smem[];
    const uint32_t sb = smem_u32(smem);
    const int tid = threadIdx.x, wid = tid >> 5, lane = tid & 31;
    const int row0 = blockIdx.x * 128;

    const __nv_bfloat16* __restrict__ Wh = (BN == 128) ? g_W1h : g_W2h;
    const __nv_bfloat16* __restrict__ Wl = (BN == 128) ? g_W1l : g_W2l;

    const int warp_m = wid & 3;
    const int warp_n = wid >> 2;

    float acc[2][NI][4];
#pragma unroll
    for (int mi = 0; mi < 2; mi++)
#pragma unroll
        for (int ni = 0; ni < NI; ni++)
#pragma unroll
            for (int q = 0; q < 4; q++) acc[mi][ni][q] = 0.f;

    auto load_tile = [&](int buf, int k0) {
        uint32_t base = sb + buf * KBUF;
#pragma unroll
        for (int i = 0; i < 2; i++) {
            int v = tid + i * 256;
            int row = v >> 2, ks = v & 3;
            uint32_t sw = SWZ64((uint32_t)(row * 64 + ks * 16));
            size_t go = (size_t)(row0 + row) * KPAD + k0 + ks * 8;
            CP_ASYNC16(base + OAH + sw, g_Hh + go);
            CP_ASYNC16(base + OAL + sw, g_Hl + go);
        }
#pragma unroll
        for (int i = 0; i < BN * 4 / 256; i++) {
            int v = tid + i * 256;
            int row = v >> 2, ks = v & 3;
            uint32_t sw = SWZ64((uint32_t)(row * 64 + ks * 16));
            size_t go = (size_t)row * KPAD + k0 + ks * 8;
            CP_ASYNC16(base + OBH + sw, Wh + go);
            CP_ASYNC16(base + OBL + sw, Wl + go);
        }
    };

    load_tile(0, 0);
    CP_COMMIT();

    for (int kt = 0; kt < 16; kt++) {
        if (kt < 15) {
            load_tile((kt + 1) & 1, (kt + 1) * 32);
            CP_COMMIT();
            CP_WAIT(1);
        } else {
            CP_WAIT(0);
        }
        __syncthreads();

        const uint32_t base = sb + (kt & 1) * KBUF;
#pragma unroll
        for (int kk = 0; kk < 2; kk++) {
            uint32_t ah[2][4], al[2][4];
#pragma unroll
            for (int mi = 0; mi < 2; mi++) {
                uint32_t off = (uint32_t)((warp_m * 32 + mi * 16 + (lane & 15)) * 64
                                          + kk * 32 + (lane >> 4) * 16);
                uint32_t sw = SWZ64(off);
                ldsm_x4(ah[mi], base + OAH + sw);
                ldsm_x4(al[mi], base + OAL + sw);
            }
            uint32_t bh[NI][2], bl[NI][2];
#pragma unroll
            for (int ni = 0; ni < NI; ni++) {
                uint32_t off = (uint32_t)((warp_n * (BN / 2) + ni * 8 + (lane & 7)) * 64
                                          + kk * 32 + ((lane >> 3) & 1) * 16);
                uint32_t sw = SWZ64(off);
                ldsm_x2(bh[ni], base + OBH + sw);
                ldsm_x2(bl[ni], base + OBL + sw);
            }
#pragma unroll
            for (int mi = 0; mi < 2; mi++)
#pragma unroll
                for (int ni = 0; ni < NI; ni++) {
                    mma16816(acc[mi][ni], ah[mi], bh[ni]);
                    mma16816(acc[mi][ni], ah[mi], bl[ni]);
                    mma16816(acc[mi][ni], al[mi], bh[ni]);
                }
        }
        __syncthreads();
    }

    // fused epilogue
    const int g = lane >> 2, t = lane & 3;
#pragma unroll
    for (int mi = 0; mi < 2; mi++) {
        const int row = row0 + warp_m * 32 + mi * 16 + g;
#pragma unroll
        for (int ni = 0; ni < NI; ni++) {
            const int col = warp_n * (BN / 2) + ni * 8 + t * 2;
            const float b0 = bias[col], b1 = bias[col + 1];
#pragma unroll
            for (int h2 = 0; h2 < 2; h2++) {
                const int rr = row + h2 * 8;
                const float vx = acc[mi][ni][h2 * 2 + 0] + b0;
                const float vy = acc[mi][ni][h2 * 2 + 1] + b1;
                if (ACT == 0) {
                    *(float2*)(g_V + (size_t)rr * 128 + col) =
                        make_float2(1.f / (1.f + __expf(-vx)),
                                    1.f / (1.f + __expf(-vy)));
                } else {
                    const int n = rr >> 7, b = rr & 127;
                    const float c0 = tanhf(vx), c1 = tanhf(vy);
                    const float u0 = g_V[(size_t)rr * 128 + 64 + col];
                    const float u1 = g_V[(size_t)rr * 128 + 64 + col + 1];
                    const size_t si = ((size_t)b * NNODE + n) * COUT_ + col;
                    const float st0 = state[si], st1 = state[si + 1];
                    *(float2*)(outp + si) =
                        make_float2(u0 * st0 + (1.f - u0) * c0,
                                    u1 * st1 + (1.f - u1) * c1);
                }
            }
        }
    }
}

// ---------------- launch ----------------------------------------------------
extern "C" void kernel_launch(void* const* d_in, const int* in_sizes, int n_in,
                              void* d_out, int out_size) {
    const float* input = (const float*)d_in[0];
    const float* state = (const float*)d_in[1];
    const float* A0    = (const float*)d_in[2];
    const float* A1    = (const float*)d_in[3];
    const float* nv1_1 = (const float*)d_in[4];
    const float* nv2_1 = (const float*)d_in[5];
    const float* W1    = (const float*)d_in[6];
    const float* b1    = (const float*)d_in[7];
    const float* nv1_2 = (const float*)d_in[8];
    const float* nv2_2 = (const float*)d_in[9];
    const float* W2    = (const float*)d_in[10];
    const float* b2    = (const float*)d_in[11];
    float* outp = (float*)d_out;

    constexpr int KO128_SMEM = 2 * (2 * 8192 + 2 * 8192);   // 65536
    constexpr int KO64_SMEM  = 2 * (2 * 8192 + 2 * 4096);   // 49152
    cudaFuncSetAttribute(k_diff_mma, cudaFuncAttributeMaxDynamicSharedMemorySize, DIFF_SMEM);
    cudaFuncSetAttribute(k_out_mma<128, 0>, cudaFuncAttributeMaxDynamicSharedMemorySize, KO128_SMEM);
    cudaFuncSetAttribute(k_out_mma<64, 1>,  cudaFuncAttributeMaxDynamicSharedMemorySize, KO64_SMEM);

    const dim3 gDiff(BF / 128, NNODE / 128, 6);      // (66, 4, 6)
    const dim3 gSrc(BF / 32, NNODE / 32);

    k_adp<<<dim3(NNODE, 2), 512>>>(nv1_1, nv2_1, nv1_2, nv2_2);
    k_prepA<<<dim3(16, 16, 4), 256>>>(A0, A1);
    k_prepW<<<dim3((KPAD * 128 + 255) / 256, 2), 256>>>(W1, W2);
    k_sq<<<dim3(4, 4, 16), 256>>>(A0, A1);
    k_splitA2<<<(4 * NNODE * NNODE + 255) / 256, 256>>>();

    // GCN 1
    k_src<<<gSrc, 256>>>(0, input, state);
    k_diff_mma<<<gDiff, 256, DIFF_SMEM>>>(0);
    k_out_mma<128, 0><<<NNODE * BB / 128, 256, KO128_SMEM>>>(b1, state, nullptr);

    // GCN 2
    k_src<<<gSrc, 256>>>(1, input, state);
    k_diff_mma<<<gDiff, 256, DIFF_SMEM>>>(1);
    k_out_mma<64, 1><<<NNODE * BB / 128, 256, KO64_SMEM>>>(b2, state, outp);
}